// round 5
// baseline (speedup 1.0000x reference)
#include <cuda_runtime.h>
#include <cuda_fp16.h>
#include <math.h>

#define NN 100000
#define NE 1600000
#define DD 128
#define NG 64
#define JK (3*DD)   // 384

#define NB_SCAN 98          // ceil(NN/1024)
#define XS_STRIDE 132
#define WS_STRIDE 136

// ---------------- scratch (device globals) ----------------
__device__ float  g_dinv[NN];
__device__ int    g_deg[NN];
__device__ int    g_inc[NN];
__device__ int    g_part[NB_SCAN];
__device__ int    g_off[NN + 1];
__device__ int    g_fill[NN];
__device__ float2 g_meta[NE];                 // {src bits, norm}, dst-sorted
__device__ __half g_half[(size_t)NN*DD];      // fp16 GEMM output (message buffer)
__device__ float  g_bufB[(size_t)NN*DD];      // layer output fp32
__device__ float  g_pooled[NG*JK];
__device__ float  g_cnt[NG];
__device__ float  g_dense[NG*DD];

// ---------------- preprocessing ----------------
__global__ void k_init() {
    int i = blockIdx.x*256 + threadIdx.x;
    if (i < NN) g_deg[i] = 0;
    if (i < NG*JK) g_pooled[i] = 0.0f;
    if (i < NG) g_cnt[i] = 0.0f;
}

__global__ void k_deg(const int* __restrict__ ei) {
    int e = blockIdx.x*256 + threadIdx.x;
    if (e < NE) atomicAdd(&g_deg[ei[NE + e]], 1);
}

__global__ void k_dinv_cnt(const int* __restrict__ batch) {
    int i = blockIdx.x*256 + threadIdx.x;
    if (i < NN) {
        g_dinv[i] = rsqrtf((float)g_deg[i] + 1.0f);
        atomicAdd(&g_cnt[batch[i]], 1.0f);
    }
}

__global__ __launch_bounds__(1024) void k_scan1() {
    __shared__ int sh[1024];
    int t = threadIdx.x;
    int i = blockIdx.x*1024 + t;
    int v = (i < NN) ? g_deg[i] : 0;
    sh[t] = v;
    __syncthreads();
    for (int off = 1; off < 1024; off <<= 1) {
        int add = (t >= off) ? sh[t - off] : 0;
        __syncthreads();
        sh[t] += add;
        __syncthreads();
    }
    if (i < NN) g_inc[i] = sh[t];
    if (t == 1023) g_part[blockIdx.x] = sh[1023];
}

// parallel exclusive scan over NB_SCAN partials (one block, 128 thr)
__global__ __launch_bounds__(128) void k_scan2() {
    __shared__ int ws[4];
    int t = threadIdx.x;
    int v = (t < NB_SCAN) ? g_part[t] : 0;
    int orig = v;
    #pragma unroll
    for (int off = 1; off < 32; off <<= 1) {
        int u = __shfl_up_sync(0xffffffffu, v, off);
        if ((t & 31) >= off) v += u;
    }
    if ((t & 31) == 31) ws[t >> 5] = v;
    __syncthreads();
    int wadd = 0;
    #pragma unroll
    for (int wq = 0; wq < 4; wq++)
        if ((t >> 5) > wq) wadd += ws[wq];
    if (t < NB_SCAN) g_part[t] = v + wadd - orig;   // exclusive
}

__global__ void k_scan3() {
    int i = blockIdx.x*256 + threadIdx.x;
    if (i < NN) {
        int off = g_inc[i] - g_deg[i] + g_part[i >> 10];
        g_off[i] = off;
        g_fill[i] = off;
    }
    if (i == 0) g_off[NN] = NE;
}

__global__ void k_reorder(const int* __restrict__ ei) {
    int e = blockIdx.x*256 + threadIdx.x;
    if (e < NE) {
        int s = ei[e];
        int d = ei[NE + e];
        int pos = atomicAdd(&g_fill[d], 1);
        float2 m;
        m.x = __int_as_float(s);
        m.y = g_dinv[s] * g_dinv[d];
        g_meta[pos] = m;
    }
}

// ---------------- tf32 tensor-core GEMM: g_half = fp16(X @ W) ----------------
__device__ __forceinline__ unsigned f2tf32(float f) {
    unsigned u;
    asm("cvt.rna.tf32.f32 %0, %1;" : "=r"(u) : "f"(f));
    return u;
}

__global__ __launch_bounds__(256, 1) void k_gemm_tc(const float* __restrict__ Xext,
                                                    const float* __restrict__ W,
                                                    int use_ext) {
    const float* X = use_ext ? Xext : g_bufB;
    extern __shared__ unsigned sh[];
    unsigned* Xs = sh;
    unsigned* Ws = sh + 128*XS_STRIDE;

    int t = threadIdx.x;
    int row0 = blockIdx.x * 128;

    for (int i = t; i < 128*32; i += 256) {
        int r = i >> 5, c4 = (i & 31) * 4;
        float4 v = *(const float4*)(W + r*128 + c4);
        unsigned* p = Ws + r*WS_STRIDE + c4;
        p[0] = f2tf32(v.x); p[1] = f2tf32(v.y); p[2] = f2tf32(v.z); p[3] = f2tf32(v.w);
    }
    for (int i = t; i < 128*32; i += 256) {
        int r = i >> 5, c4 = (i & 31) * 4;
        int row = row0 + r;
        float4 v = make_float4(0.f, 0.f, 0.f, 0.f);
        if (row < NN) v = *(const float4*)(X + (size_t)row*DD + c4);
        unsigned* p = Xs + r*XS_STRIDE + c4;
        p[0] = f2tf32(v.x); p[1] = f2tf32(v.y); p[2] = f2tf32(v.z); p[3] = f2tf32(v.w);
    }
    __syncthreads();

    int w = t >> 5, lane = t & 31;
    int gid = lane >> 2, tig = lane & 3;
    int rw = (w & 3) * 32;
    int cw = (w >> 2) * 64;

    float c[2][8][4];
    #pragma unroll
    for (int rt = 0; rt < 2; rt++)
        #pragma unroll
        for (int ct = 0; ct < 8; ct++)
            c[rt][ct][0] = c[rt][ct][1] = c[rt][ct][2] = c[rt][ct][3] = 0.f;

    #pragma unroll
    for (int ks = 0; ks < 16; ks++) {
        int k0 = ks * 8;
        unsigned a[2][4], b[8][2];
        #pragma unroll
        for (int rt = 0; rt < 2; rt++) {
            int rbase = rw + rt*16;
            a[rt][0] = Xs[(rbase + gid    )*XS_STRIDE + k0 + tig];
            a[rt][1] = Xs[(rbase + gid + 8)*XS_STRIDE + k0 + tig];
            a[rt][2] = Xs[(rbase + gid    )*XS_STRIDE + k0 + tig + 4];
            a[rt][3] = Xs[(rbase + gid + 8)*XS_STRIDE + k0 + tig + 4];
        }
        #pragma unroll
        for (int ct = 0; ct < 8; ct++) {
            int col = cw + ct*8 + gid;
            b[ct][0] = Ws[(k0 + tig    )*WS_STRIDE + col];
            b[ct][1] = Ws[(k0 + tig + 4)*WS_STRIDE + col];
        }
        #pragma unroll
        for (int rt = 0; rt < 2; rt++)
            #pragma unroll
            for (int ct = 0; ct < 8; ct++) {
                asm volatile(
                    "mma.sync.aligned.m16n8k8.row.col.f32.tf32.tf32.f32 "
                    "{%0,%1,%2,%3}, {%4,%5,%6,%7}, {%8,%9}, {%0,%1,%2,%3};"
                    : "+f"(c[rt][ct][0]), "+f"(c[rt][ct][1]),
                      "+f"(c[rt][ct][2]), "+f"(c[rt][ct][3])
                    : "r"(a[rt][0]), "r"(a[rt][1]), "r"(a[rt][2]), "r"(a[rt][3]),
                      "r"(b[ct][0]), "r"(b[ct][1]));
            }
    }

    #pragma unroll
    for (int rt = 0; rt < 2; rt++) {
        #pragma unroll
        for (int ct = 0; ct < 8; ct++) {
            int r1 = row0 + rw + rt*16 + gid;
            int col = cw + ct*8 + tig*2;
            if (r1 < NN)
                *(__half2*)(g_half + (size_t)r1*DD + col) = __floats2half2_rn(c[rt][ct][0], c[rt][ct][1]);
            int r2 = r1 + 8;
            if (r2 < NN)
                *(__half2*)(g_half + (size_t)r2*DD + col) = __floats2half2_rn(c[rt][ct][2], c[rt][ct][3]);
        }
    }
}

// ---------------- fused CSR gather: 2 edges/warp, LDG.128 rows ----------------
__device__ __forceinline__ void addrow(float* acc, uint4 r, float w) {
    __half2* h = (__half2*)&r;
    #pragma unroll
    for (int j = 0; j < 4; j++) {
        float2 f = __half22float2(h[j]);
        acc[2*j]   = fmaf(w, f.x, acc[2*j]);
        acc[2*j+1] = fmaf(w, f.y, acc[2*j+1]);
    }
}

__global__ __launch_bounds__(256) void k_gather(const float* __restrict__ bias,
                                                const int* __restrict__ batch,
                                                int off_l) {
    int n = blockIdx.x*8 + (threadIdx.x >> 5);
    if (n >= NN) return;
    int lane = threadIdx.x & 31;
    int half = lane >> 4;
    int sub  = lane & 15;

    int e0 = g_off[n];
    int cnt = g_off[n + 1] - e0;

    float acc[8];
    #pragma unroll
    for (int j = 0; j < 8; j++) acc[j] = 0.f;

    if (half == 0) {
        float di = g_dinv[n];
        uint4 r = *(const uint4*)(g_half + (size_t)n*DD + sub*8);
        addrow(acc, r, di*di);
    }

    const float2* mp = g_meta + e0;
    int idx = half;
    for (; idx + 6 < cnt; idx += 8) {
        float2 m0 = mp[idx];
        float2 m1 = mp[idx + 2];
        float2 m2 = mp[idx + 4];
        float2 m3 = mp[idx + 6];
        uint4 r0 = *(const uint4*)(g_half + (size_t)__float_as_int(m0.x)*DD + sub*8);
        uint4 r1 = *(const uint4*)(g_half + (size_t)__float_as_int(m1.x)*DD + sub*8);
        uint4 r2 = *(const uint4*)(g_half + (size_t)__float_as_int(m2.x)*DD + sub*8);
        uint4 r3 = *(const uint4*)(g_half + (size_t)__float_as_int(m3.x)*DD + sub*8);
        addrow(acc, r0, m0.y);
        addrow(acc, r1, m1.y);
        addrow(acc, r2, m2.y);
        addrow(acc, r3, m3.y);
    }
    for (; idx < cnt; idx += 2) {
        float2 m0 = mp[idx];
        uint4 r0 = *(const uint4*)(g_half + (size_t)__float_as_int(m0.x)*DD + sub*8);
        addrow(acc, r0, m0.y);
    }

    // combine the two half-warps
    #pragma unroll
    for (int j = 0; j < 8; j++)
        acc[j] += __shfl_xor_sync(0xffffffffu, acc[j], 16);

    if (half == 0) {
        float4 b0 = *(const float4*)(bias + sub*8);
        float4 b1 = *(const float4*)(bias + sub*8 + 4);
        float4 v0, v1;
        v0.x = fmaxf(acc[0] + b0.x, 0.f);
        v0.y = fmaxf(acc[1] + b0.y, 0.f);
        v0.z = fmaxf(acc[2] + b0.z, 0.f);
        v0.w = fmaxf(acc[3] + b0.w, 0.f);
        v1.x = fmaxf(acc[4] + b1.x, 0.f);
        v1.y = fmaxf(acc[5] + b1.y, 0.f);
        v1.z = fmaxf(acc[6] + b1.z, 0.f);
        v1.w = fmaxf(acc[7] + b1.w, 0.f);

        float* ob = g_bufB + (size_t)n*DD + sub*8;
        *(float4*)ob       = v0;
        *(float4*)(ob + 4) = v1;

        int g = batch[n];
        float* q = g_pooled + g*JK + off_l + sub*8;
        asm volatile("red.global.add.v4.f32 [%0], {%1,%2,%3,%4};"
                     :: "l"(q), "f"(v0.x), "f"(v0.y), "f"(v0.z), "f"(v0.w) : "memory");
        asm volatile("red.global.add.v4.f32 [%0], {%1,%2,%3,%4};"
                     :: "l"(q + 4), "f"(v1.x), "f"(v1.y), "f"(v1.z), "f"(v1.w) : "memory");
    }
}

// ---------------- head ----------------
__global__ __launch_bounds__(128) void k_head1(const float* __restrict__ l1w,
                                               const float* __restrict__ l1b) {
    int g = blockIdx.x;
    int j = threadIdx.x;
    __shared__ float ps[JK];
    float inv = 1.f / fmaxf(g_cnt[g], 1.f);
    for (int k = j; k < JK; k += 128) ps[k] = g_pooled[g*JK + k] * inv;
    __syncthreads();
    float s = l1b[j];
    #pragma unroll 4
    for (int k = 0; k < JK; k++) s = fmaf(ps[k], l1w[k*DD + j], s);
    g_dense[g*DD + j] = fmaxf(s, 0.f);
}

__global__ __launch_bounds__(64) void k_head2(const float* __restrict__ l2w,
                                              const float* __restrict__ l2b,
                                              float* __restrict__ out) {
    __shared__ float ws[DD*10];
    __shared__ float bs[10];
    int t = threadIdx.x;
    for (int i = t; i < DD*10; i += 64) ws[i] = l2w[i];
    if (t < 10) bs[t] = l2b[t];
    __syncthreads();
    if (t < NG) {
        float z[10];
        #pragma unroll
        for (int c = 0; c < 10; c++) z[c] = bs[c];
        for (int k = 0; k < DD; k++) {
            float gv = g_dense[t*DD + k];
            #pragma unroll
            for (int c = 0; c < 10; c++) z[c] = fmaf(gv, ws[k*10 + c], z[c]);
        }
        float m = z[0];
        #pragma unroll
        for (int c = 1; c < 10; c++) m = fmaxf(m, z[c]);
        float ssum = 0.f;
        #pragma unroll
        for (int c = 0; c < 10; c++) ssum += expf(z[c] - m);
        float ls = m + logf(ssum);
        #pragma unroll
        for (int c = 0; c < 10; c++) out[t*10 + c] = z[c] - ls;
    }
}

// ---------------- launch ----------------
extern "C" void kernel_launch(void* const* d_in, const int* in_sizes, int n_in,
                              void* d_out, int out_size) {
    const float* x     = (const float*)d_in[0];
    const int*   ei    = (const int*)  d_in[1];
    const int*   batch = (const int*)  d_in[2];
    const float* W1 = (const float*)d_in[4];  const float* b1 = (const float*)d_in[5];
    const float* W2 = (const float*)d_in[6];  const float* b2 = (const float*)d_in[7];
    const float* W3 = (const float*)d_in[8];  const float* b3 = (const float*)d_in[9];
    const float* l1w = (const float*)d_in[10]; const float* l1b = (const float*)d_in[11];
    const float* l2w = (const float*)d_in[12]; const float* l2b = (const float*)d_in[13];
    float* out = (float*)d_out;

    static cudaStream_t s2;
    static cudaEvent_t evRoot, evPre;
    static int once = 0;
    if (!once) {
        cudaFuncSetAttribute(k_gemm_tc, cudaFuncAttributeMaxDynamicSharedMemorySize,
                             (128*XS_STRIDE + 128*WS_STRIDE) * 4);
        cudaStreamCreateWithFlags(&s2, cudaStreamNonBlocking);
        cudaEventCreateWithFlags(&evRoot, cudaEventDisableTiming);
        cudaEventCreateWithFlags(&evPre, cudaEventDisableTiming);
        once = 1;
    }

    // fork: preprocessing on s2, layer-1 GEMM on the main stream
    cudaEventRecord(evRoot, 0);
    cudaStreamWaitEvent(s2, evRoot, 0);
    k_init    <<<(NN + 255)/256, 256, 0, s2>>>();
    k_deg     <<<(NE + 255)/256, 256, 0, s2>>>(ei);
    k_dinv_cnt<<<(NN + 255)/256, 256, 0, s2>>>(batch);
    k_scan1   <<<NB_SCAN, 1024, 0, s2>>>();
    k_scan2   <<<1, 128, 0, s2>>>();
    k_scan3   <<<(NN + 255)/256, 256, 0, s2>>>();
    k_reorder <<<(NE + 255)/256, 256, 0, s2>>>(ei);
    cudaEventRecord(evPre, s2);

    k_gemm_tc<<<(NN + 127)/128, 256, (128*XS_STRIDE + 128*WS_STRIDE)*4>>>(x, W1, 1);
    cudaStreamWaitEvent(0, evPre, 0);   // join before gather-1

    const float* Wl[3] = {W1, W2, W3};
    const float* bl[3] = {b1, b2, b3};
    for (int l = 0; l < 3; l++) {
        if (l > 0)
            k_gemm_tc<<<(NN + 127)/128, 256, (128*XS_STRIDE + 128*WS_STRIDE)*4>>>(x, Wl[l], 0);
        k_gather <<<(NN + 7)/8, 256>>>(bl[l], batch, l*DD);
    }

    k_head1<<<NG, 128>>>(l1w, l1b);
    k_head2<<<1, 64>>>(l2w, l2b, out);
}

// round 6
// speedup vs baseline: 1.2185x; 1.2185x over previous
#include <cuda_runtime.h>
#include <cuda_fp16.h>
#include <math.h>

#define NN 100000
#define NE 1600000
#define DD 128
#define NG 64
#define JK (3*DD)   // 384

#define NB_SCAN 98          // ceil(NN/1024)
#define XS_STRIDE 132
#define WS_STRIDE 136

// ---------------- scratch (device globals) ----------------
__device__ float  g_dinv[NN];
__device__ int    g_deg[NN];
__device__ int    g_inc[NN];
__device__ int    g_part[NB_SCAN];
__device__ int    g_off[NN + 1];
__device__ int    g_fill[NN];
__device__ float2 g_meta[NE];                 // {src bits, norm}, dst-sorted
__device__ __half g_half[(size_t)NN*DD];      // fp16 GEMM output (message buffer)
__device__ float  g_bufB[(size_t)NN*DD];      // layer output fp32
__device__ float  g_pooled[NG*JK];
__device__ float  g_cnt[NG];
__device__ float  g_dense[NG*DD];

// ---------------- preprocessing ----------------
__global__ void k_init() {
    int i = blockIdx.x*256 + threadIdx.x;
    if (i < NN) g_deg[i] = 0;
    if (i < NG*JK) g_pooled[i] = 0.0f;
    if (i < NG) g_cnt[i] = 0.0f;
}

__global__ void k_deg(const int* __restrict__ ei) {
    int e = blockIdx.x*256 + threadIdx.x;
    if (e < NE) atomicAdd(&g_deg[ei[NE + e]], 1);
}

__global__ void k_dinv_cnt(const int* __restrict__ batch) {
    int i = blockIdx.x*256 + threadIdx.x;
    if (i < NN) {
        g_dinv[i] = rsqrtf((float)g_deg[i] + 1.0f);
        atomicAdd(&g_cnt[batch[i]], 1.0f);
    }
}

__global__ __launch_bounds__(1024) void k_scan1() {
    __shared__ int sh[1024];
    int t = threadIdx.x;
    int i = blockIdx.x*1024 + t;
    int v = (i < NN) ? g_deg[i] : 0;
    sh[t] = v;
    __syncthreads();
    for (int off = 1; off < 1024; off <<= 1) {
        int add = (t >= off) ? sh[t - off] : 0;
        __syncthreads();
        sh[t] += add;
        __syncthreads();
    }
    if (i < NN) g_inc[i] = sh[t];
    if (t == 1023) g_part[blockIdx.x] = sh[1023];
}

// parallel exclusive scan over NB_SCAN partials (one block, 128 thr)
__global__ __launch_bounds__(128) void k_scan2() {
    __shared__ int ws[4];
    int t = threadIdx.x;
    int v = (t < NB_SCAN) ? g_part[t] : 0;
    int orig = v;
    #pragma unroll
    for (int off = 1; off < 32; off <<= 1) {
        int u = __shfl_up_sync(0xffffffffu, v, off);
        if ((t & 31) >= off) v += u;
    }
    if ((t & 31) == 31) ws[t >> 5] = v;
    __syncthreads();
    int wadd = 0;
    #pragma unroll
    for (int wq = 0; wq < 4; wq++)
        if ((t >> 5) > wq) wadd += ws[wq];
    if (t < NB_SCAN) g_part[t] = v + wadd - orig;   // exclusive
}

__global__ void k_scan3() {
    int i = blockIdx.x*256 + threadIdx.x;
    if (i < NN) {
        int off = g_inc[i] - g_deg[i] + g_part[i >> 10];
        g_off[i] = off;
        g_fill[i] = off;
    }
    if (i == 0) g_off[NN] = NE;
}

__global__ void k_reorder(const int* __restrict__ ei) {
    int e = blockIdx.x*256 + threadIdx.x;
    if (e < NE) {
        int s = ei[e];
        int d = ei[NE + e];
        int pos = atomicAdd(&g_fill[d], 1);
        float2 m;
        m.x = __int_as_float(s);
        m.y = g_dinv[s] * g_dinv[d];
        g_meta[pos] = m;
    }
}

// ---------------- tf32 tensor-core GEMM: g_half = fp16(X @ W) ----------------
__device__ __forceinline__ unsigned f2tf32(float f) {
    unsigned u;
    asm("cvt.rna.tf32.f32 %0, %1;" : "=r"(u) : "f"(f));
    return u;
}

__global__ __launch_bounds__(256, 1) void k_gemm_tc(const float* __restrict__ Xext,
                                                    const float* __restrict__ W,
                                                    int use_ext) {
    const float* X = use_ext ? Xext : g_bufB;
    extern __shared__ unsigned sh[];
    unsigned* Xs = sh;
    unsigned* Ws = sh + 128*XS_STRIDE;

    int t = threadIdx.x;
    int row0 = blockIdx.x * 128;

    for (int i = t; i < 128*32; i += 256) {
        int r = i >> 5, c4 = (i & 31) * 4;
        float4 v = *(const float4*)(W + r*128 + c4);
        unsigned* p = Ws + r*WS_STRIDE + c4;
        p[0] = f2tf32(v.x); p[1] = f2tf32(v.y); p[2] = f2tf32(v.z); p[3] = f2tf32(v.w);
    }
    for (int i = t; i < 128*32; i += 256) {
        int r = i >> 5, c4 = (i & 31) * 4;
        int row = row0 + r;
        float4 v = make_float4(0.f, 0.f, 0.f, 0.f);
        if (row < NN) v = *(const float4*)(X + (size_t)row*DD + c4);
        unsigned* p = Xs + r*XS_STRIDE + c4;
        p[0] = f2tf32(v.x); p[1] = f2tf32(v.y); p[2] = f2tf32(v.z); p[3] = f2tf32(v.w);
    }
    __syncthreads();

    int w = t >> 5, lane = t & 31;
    int gid = lane >> 2, tig = lane & 3;
    int rw = (w & 3) * 32;
    int cw = (w >> 2) * 64;

    float c[2][8][4];
    #pragma unroll
    for (int rt = 0; rt < 2; rt++)
        #pragma unroll
        for (int ct = 0; ct < 8; ct++)
            c[rt][ct][0] = c[rt][ct][1] = c[rt][ct][2] = c[rt][ct][3] = 0.f;

    #pragma unroll
    for (int ks = 0; ks < 16; ks++) {
        int k0 = ks * 8;
        unsigned a[2][4], b[8][2];
        #pragma unroll
        for (int rt = 0; rt < 2; rt++) {
            int rbase = rw + rt*16;
            a[rt][0] = Xs[(rbase + gid    )*XS_STRIDE + k0 + tig];
            a[rt][1] = Xs[(rbase + gid + 8)*XS_STRIDE + k0 + tig];
            a[rt][2] = Xs[(rbase + gid    )*XS_STRIDE + k0 + tig + 4];
            a[rt][3] = Xs[(rbase + gid + 8)*XS_STRIDE + k0 + tig + 4];
        }
        #pragma unroll
        for (int ct = 0; ct < 8; ct++) {
            int col = cw + ct*8 + gid;
            b[ct][0] = Ws[(k0 + tig    )*WS_STRIDE + col];
            b[ct][1] = Ws[(k0 + tig + 4)*WS_STRIDE + col];
        }
        #pragma unroll
        for (int rt = 0; rt < 2; rt++)
            #pragma unroll
            for (int ct = 0; ct < 8; ct++) {
                asm volatile(
                    "mma.sync.aligned.m16n8k8.row.col.f32.tf32.tf32.f32 "
                    "{%0,%1,%2,%3}, {%4,%5,%6,%7}, {%8,%9}, {%0,%1,%2,%3};"
                    : "+f"(c[rt][ct][0]), "+f"(c[rt][ct][1]),
                      "+f"(c[rt][ct][2]), "+f"(c[rt][ct][3])
                    : "r"(a[rt][0]), "r"(a[rt][1]), "r"(a[rt][2]), "r"(a[rt][3]),
                      "r"(b[ct][0]), "r"(b[ct][1]));
            }
    }

    #pragma unroll
    for (int rt = 0; rt < 2; rt++) {
        #pragma unroll
        for (int ct = 0; ct < 8; ct++) {
            int r1 = row0 + rw + rt*16 + gid;
            int col = cw + ct*8 + tig*2;
            if (r1 < NN)
                *(__half2*)(g_half + (size_t)r1*DD + col) = __floats2half2_rn(c[rt][ct][0], c[rt][ct][1]);
            int r2 = r1 + 8;
            if (r2 < NN)
                *(__half2*)(g_half + (size_t)r2*DD + col) = __floats2half2_rn(c[rt][ct][2], c[rt][ct][3]);
        }
    }
}

// ---------------- fused CSR gather: 2 edges/warp, LDG.128 rows ----------------
__device__ __forceinline__ void addrow(float* acc, uint4 r, float w) {
    __half2* h = (__half2*)&r;
    #pragma unroll
    for (int j = 0; j < 4; j++) {
        float2 f = __half22float2(h[j]);
        acc[2*j]   = fmaf(w, f.x, acc[2*j]);
        acc[2*j+1] = fmaf(w, f.y, acc[2*j+1]);
    }
}

__global__ __launch_bounds__(256) void k_gather(const float* __restrict__ bias,
                                                const int* __restrict__ batch,
                                                int off_l) {
    int n = blockIdx.x*8 + (threadIdx.x >> 5);
    if (n >= NN) return;
    int lane = threadIdx.x & 31;
    int half = lane >> 4;
    int sub  = lane & 15;

    int e0 = g_off[n];
    int cnt = g_off[n + 1] - e0;

    float acc[8];
    #pragma unroll
    for (int j = 0; j < 8; j++) acc[j] = 0.f;

    if (half == 0) {
        float di = g_dinv[n];
        uint4 r = *(const uint4*)(g_half + (size_t)n*DD + sub*8);
        addrow(acc, r, di*di);
    }

    const float2* mp = g_meta + e0;
    int idx = half;
    for (; idx + 6 < cnt; idx += 8) {
        float2 m0 = mp[idx];
        float2 m1 = mp[idx + 2];
        float2 m2 = mp[idx + 4];
        float2 m3 = mp[idx + 6];
        uint4 r0 = *(const uint4*)(g_half + (size_t)__float_as_int(m0.x)*DD + sub*8);
        uint4 r1 = *(const uint4*)(g_half + (size_t)__float_as_int(m1.x)*DD + sub*8);
        uint4 r2 = *(const uint4*)(g_half + (size_t)__float_as_int(m2.x)*DD + sub*8);
        uint4 r3 = *(const uint4*)(g_half + (size_t)__float_as_int(m3.x)*DD + sub*8);
        addrow(acc, r0, m0.y);
        addrow(acc, r1, m1.y);
        addrow(acc, r2, m2.y);
        addrow(acc, r3, m3.y);
    }
    for (; idx < cnt; idx += 2) {
        float2 m0 = mp[idx];
        uint4 r0 = *(const uint4*)(g_half + (size_t)__float_as_int(m0.x)*DD + sub*8);
        addrow(acc, r0, m0.y);
    }

    // combine the two half-warps
    #pragma unroll
    for (int j = 0; j < 8; j++)
        acc[j] += __shfl_xor_sync(0xffffffffu, acc[j], 16);

    if (half == 0) {
        float4 b0 = *(const float4*)(bias + sub*8);
        float4 b1 = *(const float4*)(bias + sub*8 + 4);
        float4 v0, v1;
        v0.x = fmaxf(acc[0] + b0.x, 0.f);
        v0.y = fmaxf(acc[1] + b0.y, 0.f);
        v0.z = fmaxf(acc[2] + b0.z, 0.f);
        v0.w = fmaxf(acc[3] + b0.w, 0.f);
        v1.x = fmaxf(acc[4] + b1.x, 0.f);
        v1.y = fmaxf(acc[5] + b1.y, 0.f);
        v1.z = fmaxf(acc[6] + b1.z, 0.f);
        v1.w = fmaxf(acc[7] + b1.w, 0.f);

        float* ob = g_bufB + (size_t)n*DD + sub*8;
        *(float4*)ob       = v0;
        *(float4*)(ob + 4) = v1;

        int g = batch[n];
        float* q = g_pooled + g*JK + off_l + sub*8;
        asm volatile("red.global.add.v4.f32 [%0], {%1,%2,%3,%4};"
                     :: "l"(q), "f"(v0.x), "f"(v0.y), "f"(v0.z), "f"(v0.w) : "memory");
        asm volatile("red.global.add.v4.f32 [%0], {%1,%2,%3,%4};"
                     :: "l"(q + 4), "f"(v1.x), "f"(v1.y), "f"(v1.z), "f"(v1.w) : "memory");
    }
}

// ---------------- head ----------------
__global__ __launch_bounds__(128) void k_head1(const float* __restrict__ l1w,
                                               const float* __restrict__ l1b) {
    int g = blockIdx.x;
    int j = threadIdx.x;
    __shared__ float ps[JK];
    float inv = 1.f / fmaxf(g_cnt[g], 1.f);
    for (int k = j; k < JK; k += 128) ps[k] = g_pooled[g*JK + k] * inv;
    __syncthreads();
    float s = l1b[j];
    #pragma unroll 4
    for (int k = 0; k < JK; k++) s = fmaf(ps[k], l1w[k*DD + j], s);
    g_dense[g*DD + j] = fmaxf(s, 0.f);
}

__global__ __launch_bounds__(64) void k_head2(const float* __restrict__ l2w,
                                              const float* __restrict__ l2b,
                                              float* __restrict__ out) {
    __shared__ float ws[DD*10];
    __shared__ float bs[10];
    int t = threadIdx.x;
    for (int i = t; i < DD*10; i += 64) ws[i] = l2w[i];
    if (t < 10) bs[t] = l2b[t];
    __syncthreads();
    if (t < NG) {
        float z[10];
        #pragma unroll
        for (int c = 0; c < 10; c++) z[c] = bs[c];
        for (int k = 0; k < DD; k++) {
            float gv = g_dense[t*DD + k];
            #pragma unroll
            for (int c = 0; c < 10; c++) z[c] = fmaf(gv, ws[k*10 + c], z[c]);
        }
        float m = z[0];
        #pragma unroll
        for (int c = 1; c < 10; c++) m = fmaxf(m, z[c]);
        float ssum = 0.f;
        #pragma unroll
        for (int c = 0; c < 10; c++) ssum += expf(z[c] - m);
        float ls = m + logf(ssum);
        #pragma unroll
        for (int c = 0; c < 10; c++) out[t*10 + c] = z[c] - ls;
    }
}

// ---------------- launch (serial, single stream — fork reverted) ----------------
extern "C" void kernel_launch(void* const* d_in, const int* in_sizes, int n_in,
                              void* d_out, int out_size) {
    const float* x     = (const float*)d_in[0];
    const int*   ei    = (const int*)  d_in[1];
    const int*   batch = (const int*)  d_in[2];
    const float* W1 = (const float*)d_in[4];  const float* b1 = (const float*)d_in[5];
    const float* W2 = (const float*)d_in[6];  const float* b2 = (const float*)d_in[7];
    const float* W3 = (const float*)d_in[8];  const float* b3 = (const float*)d_in[9];
    const float* l1w = (const float*)d_in[10]; const float* l1b = (const float*)d_in[11];
    const float* l2w = (const float*)d_in[12]; const float* l2b = (const float*)d_in[13];
    float* out = (float*)d_out;

    static int once = 0;
    if (!once) {
        cudaFuncSetAttribute(k_gemm_tc, cudaFuncAttributeMaxDynamicSharedMemorySize,
                             (128*XS_STRIDE + 128*WS_STRIDE) * 4);
        once = 1;
    }

    k_init    <<<(NN + 255)/256, 256>>>();
    k_deg     <<<(NE + 255)/256, 256>>>(ei);
    k_dinv_cnt<<<(NN + 255)/256, 256>>>(batch);
    k_scan1   <<<NB_SCAN, 1024>>>();
    k_scan2   <<<1, 128>>>();
    k_scan3   <<<(NN + 255)/256, 256>>>();
    k_reorder <<<(NE + 255)/256, 256>>>(ei);

    const float* Wl[3] = {W1, W2, W3};
    const float* bl[3] = {b1, b2, b3};
    for (int l = 0; l < 3; l++) {
        k_gemm_tc<<<(NN + 127)/128, 256, (128*XS_STRIDE + 128*WS_STRIDE)*4>>>(x, Wl[l], l == 0 ? 1 : 0);
        k_gather <<<(NN + 7)/8, 256>>>(bl[l], batch, l*DD);
    }

    k_head1<<<NG, 128>>>(l1w, l1b);
    k_head2<<<1, 64>>>(l2w, l2b, out);
}

// round 8
// speedup vs baseline: 1.3027x; 1.0691x over previous
#include <cuda_runtime.h>
#include <cuda_fp16.h>
#include <math.h>

#define NN 100000
#define NE 1600000
#define DD 128
#define NG 64
#define JK (3*DD)   // 384

#define NB_SCAN 98          // ceil(NN/1024)
#define XS_STRIDE 132
#define WS_STRIDE 136

// ---------------- scratch (device globals) ----------------
__device__ float  g_dinv[NN];
__device__ int    g_deg[NN];
__device__ int    g_inc[NN];
__device__ int    g_part[NB_SCAN];
__device__ int    g_off[NN + 1];
__device__ int    g_fill[NN];
__device__ float2 g_meta[NE];                 // {src bits, norm}, dst-sorted
__device__ __half g_half[(size_t)NN*DD];      // fp16 GEMM output (message buffer)
__device__ float  g_bufB[(size_t)NN*DD];      // layer output fp32
__device__ float  g_pooled[NG*JK];
__device__ float  g_cnt[NG];
__device__ float  g_dense[NG*DD];

// ---------------- preprocessing ----------------
__global__ void k_init() {
    int i = blockIdx.x*256 + threadIdx.x;
    if (i < NN) g_deg[i] = 0;
    if (i < NG*JK) g_pooled[i] = 0.0f;
    if (i < NG) g_cnt[i] = 0.0f;
}

__global__ void k_deg(const int* __restrict__ ei) {
    int e = blockIdx.x*256 + threadIdx.x;
    if (e < NE) atomicAdd(&g_deg[ei[NE + e]], 1);
}

__global__ void k_dinv_cnt(const int* __restrict__ batch) {
    int i = blockIdx.x*256 + threadIdx.x;
    if (i < NN) {
        g_dinv[i] = rsqrtf((float)g_deg[i] + 1.0f);
        atomicAdd(&g_cnt[batch[i]], 1.0f);
    }
}

__global__ __launch_bounds__(1024) void k_scan1() {
    __shared__ int sh[1024];
    int t = threadIdx.x;
    int i = blockIdx.x*1024 + t;
    int v = (i < NN) ? g_deg[i] : 0;
    sh[t] = v;
    __syncthreads();
    for (int off = 1; off < 1024; off <<= 1) {
        int add = (t >= off) ? sh[t - off] : 0;
        __syncthreads();
        sh[t] += add;
        __syncthreads();
    }
    if (i < NN) g_inc[i] = sh[t];
    if (t == 1023) g_part[blockIdx.x] = sh[1023];
}

__global__ __launch_bounds__(128) void k_scan2() {
    __shared__ int ws[4];
    int t = threadIdx.x;
    int v = (t < NB_SCAN) ? g_part[t] : 0;
    int orig = v;
    #pragma unroll
    for (int off = 1; off < 32; off <<= 1) {
        int u = __shfl_up_sync(0xffffffffu, v, off);
        if ((t & 31) >= off) v += u;
    }
    if ((t & 31) == 31) ws[t >> 5] = v;
    __syncthreads();
    int wadd = 0;
    #pragma unroll
    for (int wq = 0; wq < 4; wq++)
        if ((t >> 5) > wq) wadd += ws[wq];
    if (t < NB_SCAN) g_part[t] = v + wadd - orig;   // exclusive
}

__global__ void k_scan3() {
    int i = blockIdx.x*256 + threadIdx.x;
    if (i < NN) {
        int off = g_inc[i] - g_deg[i] + g_part[i >> 10];
        g_off[i] = off;
        g_fill[i] = off;
    }
    if (i == 0) g_off[NN] = NE;
}

__global__ void k_reorder(const int* __restrict__ ei) {
    int e = blockIdx.x*256 + threadIdx.x;
    if (e < NE) {
        int s = ei[e];
        int d = ei[NE + e];
        int pos = atomicAdd(&g_fill[d], 1);
        float2 m;
        m.x = __int_as_float(s);
        m.y = g_dinv[s] * g_dinv[d];
        g_meta[pos] = m;
    }
}

// ---------------- tf32 tensor-core GEMM: g_half = fp16(X @ W) ----------------
__device__ __forceinline__ unsigned f2tf32(float f) {
    unsigned u;
    asm("cvt.rna.tf32.f32 %0, %1;" : "=r"(u) : "f"(f));
    return u;
}

__global__ __launch_bounds__(256, 1) void k_gemm_tc(const float* __restrict__ Xext,
                                                    const float* __restrict__ W,
                                                    int use_ext) {
    const float* X = use_ext ? Xext : g_bufB;
    extern __shared__ unsigned sh[];
    unsigned* Xs = sh;
    unsigned* Ws = sh + 128*XS_STRIDE;

    int t = threadIdx.x;
    int row0 = blockIdx.x * 128;

    for (int i = t; i < 128*32; i += 256) {
        int r = i >> 5, c4 = (i & 31) * 4;
        float4 v = *(const float4*)(W + r*128 + c4);
        unsigned* p = Ws + r*WS_STRIDE + c4;
        p[0] = f2tf32(v.x); p[1] = f2tf32(v.y); p[2] = f2tf32(v.z); p[3] = f2tf32(v.w);
    }
    for (int i = t; i < 128*32; i += 256) {
        int r = i >> 5, c4 = (i & 31) * 4;
        int row = row0 + r;
        float4 v = make_float4(0.f, 0.f, 0.f, 0.f);
        if (row < NN) v = *(const float4*)(X + (size_t)row*DD + c4);
        unsigned* p = Xs + r*XS_STRIDE + c4;
        p[0] = f2tf32(v.x); p[1] = f2tf32(v.y); p[2] = f2tf32(v.z); p[3] = f2tf32(v.w);
    }
    __syncthreads();

    int w = t >> 5, lane = t & 31;
    int gid = lane >> 2, tig = lane & 3;
    int rw = (w & 3) * 32;
    int cw = (w >> 2) * 64;

    float c[2][8][4];
    #pragma unroll
    for (int rt = 0; rt < 2; rt++)
        #pragma unroll
        for (int ct = 0; ct < 8; ct++)
            c[rt][ct][0] = c[rt][ct][1] = c[rt][ct][2] = c[rt][ct][3] = 0.f;

    #pragma unroll
    for (int ks = 0; ks < 16; ks++) {
        int k0 = ks * 8;
        unsigned a[2][4], b[8][2];
        #pragma unroll
        for (int rt = 0; rt < 2; rt++) {
            int rbase = rw + rt*16;
            a[rt][0] = Xs[(rbase + gid    )*XS_STRIDE + k0 + tig];
            a[rt][1] = Xs[(rbase + gid + 8)*XS_STRIDE + k0 + tig];
            a[rt][2] = Xs[(rbase + gid    )*XS_STRIDE + k0 + tig + 4];
            a[rt][3] = Xs[(rbase + gid + 8)*XS_STRIDE + k0 + tig + 4];
        }
        #pragma unroll
        for (int ct = 0; ct < 8; ct++) {
            int col = cw + ct*8 + gid;
            b[ct][0] = Ws[(k0 + tig    )*WS_STRIDE + col];
            b[ct][1] = Ws[(k0 + tig + 4)*WS_STRIDE + col];
        }
        #pragma unroll
        for (int rt = 0; rt < 2; rt++)
            #pragma unroll
            for (int ct = 0; ct < 8; ct++) {
                asm volatile(
                    "mma.sync.aligned.m16n8k8.row.col.f32.tf32.tf32.f32 "
                    "{%0,%1,%2,%3}, {%4,%5,%6,%7}, {%8,%9}, {%0,%1,%2,%3};"
                    : "+f"(c[rt][ct][0]), "+f"(c[rt][ct][1]),
                      "+f"(c[rt][ct][2]), "+f"(c[rt][ct][3])
                    : "r"(a[rt][0]), "r"(a[rt][1]), "r"(a[rt][2]), "r"(a[rt][3]),
                      "r"(b[ct][0]), "r"(b[ct][1]));
            }
    }

    #pragma unroll
    for (int rt = 0; rt < 2; rt++) {
        #pragma unroll
        for (int ct = 0; ct < 8; ct++) {
            int r1 = row0 + rw + rt*16 + gid;
            int col = cw + ct*8 + tig*2;
            if (r1 < NN)
                *(__half2*)(g_half + (size_t)r1*DD + col) = __floats2half2_rn(c[rt][ct][0], c[rt][ct][1]);
            int r2 = r1 + 8;
            if (r2 < NN)
                *(__half2*)(g_half + (size_t)r2*DD + col) = __floats2half2_rn(c[rt][ct][2], c[rt][ct][3]);
        }
    }
}

// ---------------- fused CSR gather (R4 shape + pipelined metas) ----------------
__device__ __forceinline__ float4 h4tof4(uint2 r) {
    __half2 a = *(__half2*)&r.x;
    __half2 b = *(__half2*)&r.y;
    float2 fa = __half22float2(a), fb = __half22float2(b);
    return make_float4(fa.x, fa.y, fb.x, fb.y);
}

__device__ __forceinline__ void fma4(float4& acc, float w, float4 v) {
    acc.x = fmaf(w, v.x, acc.x);
    acc.y = fmaf(w, v.y, acc.y);
    acc.z = fmaf(w, v.z, acc.z);
    acc.w = fmaf(w, v.w, acc.w);
}

__global__ __launch_bounds__(256) void k_gather(const float* __restrict__ bias,
                                                const int* __restrict__ batch,
                                                int off_l) {
    int n = blockIdx.x*8 + (threadIdx.x >> 5);
    if (n >= NN) return;
    int lane = threadIdx.x & 31;

    int e0 = g_off[n];
    int e1 = g_off[n + 1];
    float di = g_dinv[n];

    uint2 sraw = *(const uint2*)(g_half + (size_t)n*DD + lane*4);
    float4 sv = h4tof4(sraw);
    float w = di * di;
    float4 acc = make_float4(w*sv.x, w*sv.y, w*sv.z, w*sv.w);

    int e = e0;
    // peel one edge to make e even (16B-aligned float4 meta loads)
    if ((e & 1) && e < e1) {
        float2 m = g_meta[e];
        uint2 r = *(const uint2*)(g_half + (size_t)__float_as_int(m.x)*DD + lane*4);
        fma4(acc, m.y, h4tof4(r));
        e++;
    }

    if (e + 4 <= e1) {
        // prime: metas for the first quad
        float4 ma = *(const float4*)(g_meta + e);       // edges e, e+1
        float4 mb = *(const float4*)(g_meta + e + 2);   // edges e+2, e+3
        while (e + 8 <= e1) {
            // issue row loads for current quad
            uint2 r0 = *(const uint2*)(g_half + (size_t)__float_as_int(ma.x)*DD + lane*4);
            uint2 r1 = *(const uint2*)(g_half + (size_t)__float_as_int(ma.z)*DD + lane*4);
            uint2 r2 = *(const uint2*)(g_half + (size_t)__float_as_int(mb.x)*DD + lane*4);
            uint2 r3 = *(const uint2*)(g_half + (size_t)__float_as_int(mb.z)*DD + lane*4);
            // prefetch next quad's metas while rows are in flight
            float4 na = *(const float4*)(g_meta + e + 4);
            float4 nb = *(const float4*)(g_meta + e + 6);
            fma4(acc, ma.y, h4tof4(r0));
            fma4(acc, ma.w, h4tof4(r1));
            fma4(acc, mb.y, h4tof4(r2));
            fma4(acc, mb.w, h4tof4(r3));
            ma = na; mb = nb;
            e += 4;
        }
        // drain the primed quad
        {
            uint2 r0 = *(const uint2*)(g_half + (size_t)__float_as_int(ma.x)*DD + lane*4);
            uint2 r1 = *(const uint2*)(g_half + (size_t)__float_as_int(ma.z)*DD + lane*4);
            uint2 r2 = *(const uint2*)(g_half + (size_t)__float_as_int(mb.x)*DD + lane*4);
            uint2 r3 = *(const uint2*)(g_half + (size_t)__float_as_int(mb.z)*DD + lane*4);
            fma4(acc, ma.y, h4tof4(r0));
            fma4(acc, ma.w, h4tof4(r1));
            fma4(acc, mb.y, h4tof4(r2));
            fma4(acc, mb.w, h4tof4(r3));
            e += 4;
        }
    }
    for (; e < e1; e++) {
        float2 m = g_meta[e];
        uint2 r = *(const uint2*)(g_half + (size_t)__float_as_int(m.x)*DD + lane*4);
        fma4(acc, m.y, h4tof4(r));
    }

    float4 b4 = ((const float4*)bias)[lane];
    acc.x = fmaxf(acc.x + b4.x, 0.f);
    acc.y = fmaxf(acc.y + b4.y, 0.f);
    acc.z = fmaxf(acc.z + b4.z, 0.f);
    acc.w = fmaxf(acc.w + b4.w, 0.f);

    *(float4*)(g_bufB + (size_t)n*DD + lane*4) = acc;

    int g = batch[n];
    float* q = g_pooled + g*JK + off_l + lane*4;
    asm volatile("red.global.add.v4.f32 [%0], {%1,%2,%3,%4};"
                 :: "l"(q), "f"(acc.x), "f"(acc.y), "f"(acc.z), "f"(acc.w) : "memory");
}

// ---------------- head ----------------
__global__ __launch_bounds__(128) void k_head1(const float* __restrict__ l1w,
                                               const float* __restrict__ l1b) {
    int g = blockIdx.x;
    int j = threadIdx.x;
    __shared__ float ps[JK];
    float inv = 1.f / fmaxf(g_cnt[g], 1.f);
    for (int k = j; k < JK; k += 128) ps[k] = g_pooled[g*JK + k] * inv;
    __syncthreads();
    float s = l1b[j];
    #pragma unroll 4
    for (int k = 0; k < JK; k++) s = fmaf(ps[k], l1w[k*DD + j], s);
    g_dense[g*DD + j] = fmaxf(s, 0.f);
}

__global__ __launch_bounds__(64) void k_head2(const float* __restrict__ l2w,
                                              const float* __restrict__ l2b,
                                              float* __restrict__ out) {
    __shared__ float ws[DD*10];
    __shared__ float bs[10];
    int t = threadIdx.x;
    for (int i = t; i < DD*10; i += 64) ws[i] = l2w[i];
    if (t < 10) bs[t] = l2b[t];
    __syncthreads();
    if (t < NG) {
        float z[10];
        #pragma unroll
        for (int c = 0; c < 10; c++) z[c] = bs[c];
        for (int k = 0; k < DD; k++) {
            float gv = g_dense[t*DD + k];
            #pragma unroll
            for (int c = 0; c < 10; c++) z[c] = fmaf(gv, ws[k*10 + c], z[c]);
        }
        float m = z[0];
        #pragma unroll
        for (int c = 1; c < 10; c++) m = fmaxf(m, z[c]);
        float ssum = 0.f;
        #pragma unroll
        for (int c = 0; c < 10; c++) ssum += expf(z[c] - m);
        float ls = m + logf(ssum);
        #pragma unroll
        for (int c = 0; c < 10; c++) out[t*10 + c] = z[c] - ls;
    }
}

// ---------------- launch (serial, single stream) ----------------
extern "C" void kernel_launch(void* const* d_in, const int* in_sizes, int n_in,
                              void* d_out, int out_size) {
    const float* x     = (const float*)d_in[0];
    const int*   ei    = (const int*)  d_in[1];
    const int*   batch = (const int*)  d_in[2];
    const float* W1 = (const float*)d_in[4];  const float* b1 = (const float*)d_in[5];
    const float* W2 = (const float*)d_in[6];  const float* b2 = (const float*)d_in[7];
    const float* W3 = (const float*)d_in[8];  const float* b3 = (const float*)d_in[9];
    const float* l1w = (const float*)d_in[10]; const float* l1b = (const float*)d_in[11];
    const float* l2w = (const float*)d_in[12]; const float* l2b = (const float*)d_in[13];
    float* out = (float*)d_out;

    static int once = 0;
    if (!once) {
        cudaFuncSetAttribute(k_gemm_tc, cudaFuncAttributeMaxDynamicSharedMemorySize,
                             (128*XS_STRIDE + 128*WS_STRIDE) * 4);
        once = 1;
    }

    k_init    <<<(NN + 255)/256, 256>>>();
    k_deg     <<<(NE + 255)/256, 256>>>(ei);
    k_dinv_cnt<<<(NN + 255)/256, 256>>>(batch);
    k_scan1   <<<NB_SCAN, 1024>>>();
    k_scan2   <<<1, 128>>>();
    k_scan3   <<<(NN + 255)/256, 256>>>();
    k_reorder <<<(NE + 255)/256, 256>>>(ei);

    const float* Wl[3] = {W1, W2, W3};
    const float* bl[3] = {b1, b2, b3};
    for (int l = 0; l < 3; l++) {
        k_gemm_tc<<<(NN + 127)/128, 256, (128*XS_STRIDE + 128*WS_STRIDE)*4>>>(x, Wl[l], l == 0 ? 1 : 0);
        k_gather <<<(NN + 7)/8, 256>>>(bl[l], batch, l*DD);
    }

    k_head1<<<NG, 128>>>(l1w, l1b);
    k_head2<<<1, 64>>>(l2w, l2b, out);
}

// round 9
// speedup vs baseline: 1.6881x; 1.2959x over previous
#include <cuda_runtime.h>
#include <cuda_fp16.h>
#include <math.h>

#define NN 100000
#define NE 1600000
#define DD 128
#define NG 64
#define JK (3*DD)   // 384

#define NB_SCAN 98          // ceil(NN/1024)
#define XS_STRIDE 132
#define WS_STRIDE 136

// ---------------- scratch (device globals) ----------------
__device__ float  g_dinv[NN];
__device__ int    g_deg[NN];
__device__ int    g_inc[NN];
__device__ int    g_part[NB_SCAN];
__device__ int    g_off[NN + 1];
__device__ int    g_fill[NN];
__device__ float2 g_meta[NE];                 // {src bits, norm}, dst-sorted
__device__ __half g_half[(size_t)NN*DD];      // fp16 GEMM output (message buffer)
__device__ float  g_bufB[(size_t)NN*DD];      // layer output fp32
__device__ float  g_pooled[NG*JK];
__device__ float  g_cnt[NG];
__device__ float  g_dense[NG*DD];

// ---------------- preprocessing ----------------
__global__ void k_init() {
    int i = blockIdx.x*256 + threadIdx.x;
    if (i < NN) g_deg[i] = 0;
    if (i < NG*JK) g_pooled[i] = 0.0f;
    if (i < NG) g_cnt[i] = 0.0f;
}

__global__ void k_deg(const int* __restrict__ ei) {
    int e = blockIdx.x*256 + threadIdx.x;
    if (e < NE) atomicAdd(&g_deg[ei[NE + e]], 1);
}

__global__ void k_dinv_cnt(const int* __restrict__ batch) {
    int i = blockIdx.x*256 + threadIdx.x;
    if (i < NN) {
        g_dinv[i] = rsqrtf((float)g_deg[i] + 1.0f);
        atomicAdd(&g_cnt[batch[i]], 1.0f);
    }
}

__global__ __launch_bounds__(1024) void k_scan1() {
    __shared__ int sh[1024];
    int t = threadIdx.x;
    int i = blockIdx.x*1024 + t;
    int v = (i < NN) ? g_deg[i] : 0;
    sh[t] = v;
    __syncthreads();
    for (int off = 1; off < 1024; off <<= 1) {
        int add = (t >= off) ? sh[t - off] : 0;
        __syncthreads();
        sh[t] += add;
        __syncthreads();
    }
    if (i < NN) g_inc[i] = sh[t];
    if (t == 1023) g_part[blockIdx.x] = sh[1023];
}

__global__ __launch_bounds__(128) void k_scan2() {
    __shared__ int ws[4];
    int t = threadIdx.x;
    int v = (t < NB_SCAN) ? g_part[t] : 0;
    int orig = v;
    #pragma unroll
    for (int off = 1; off < 32; off <<= 1) {
        int u = __shfl_up_sync(0xffffffffu, v, off);
        if ((t & 31) >= off) v += u;
    }
    if ((t & 31) == 31) ws[t >> 5] = v;
    __syncthreads();
    int wadd = 0;
    #pragma unroll
    for (int wq = 0; wq < 4; wq++)
        if ((t >> 5) > wq) wadd += ws[wq];
    if (t < NB_SCAN) g_part[t] = v + wadd - orig;   // exclusive
}

__global__ void k_scan3() {
    int i = blockIdx.x*256 + threadIdx.x;
    if (i < NN) {
        int off = g_inc[i] - g_deg[i] + g_part[i >> 10];
        g_off[i] = off;
        g_fill[i] = off;
    }
    if (i == 0) g_off[NN] = NE;
}

__global__ void k_reorder(const int* __restrict__ ei) {
    int e = blockIdx.x*256 + threadIdx.x;
    if (e < NE) {
        int s = ei[e];
        int d = ei[NE + e];
        int pos = atomicAdd(&g_fill[d], 1);
        float2 m;
        m.x = __int_as_float(s);
        m.y = g_dinv[s] * g_dinv[d];
        g_meta[pos] = m;
    }
}

// ---------------- tf32 tensor-core GEMM: g_half = fp16(X @ W) ----------------
__device__ __forceinline__ unsigned f2tf32(float f) {
    unsigned u;
    asm("cvt.rna.tf32.f32 %0, %1;" : "=r"(u) : "f"(f));
    return u;
}

__global__ __launch_bounds__(256, 1) void k_gemm_tc(const float* __restrict__ Xext,
                                                    const float* __restrict__ W,
                                                    int use_ext) {
    const float* X = use_ext ? Xext : g_bufB;
    extern __shared__ unsigned sh[];
    unsigned* Xs = sh;
    unsigned* Ws = sh + 128*XS_STRIDE;

    int t = threadIdx.x;
    int row0 = blockIdx.x * 128;

    for (int i = t; i < 128*32; i += 256) {
        int r = i >> 5, c4 = (i & 31) * 4;
        float4 v = *(const float4*)(W + r*128 + c4);
        unsigned* p = Ws + r*WS_STRIDE + c4;
        p[0] = f2tf32(v.x); p[1] = f2tf32(v.y); p[2] = f2tf32(v.z); p[3] = f2tf32(v.w);
    }
    for (int i = t; i < 128*32; i += 256) {
        int r = i >> 5, c4 = (i & 31) * 4;
        int row = row0 + r;
        float4 v = make_float4(0.f, 0.f, 0.f, 0.f);
        if (row < NN) v = *(const float4*)(X + (size_t)row*DD + c4);
        unsigned* p = Xs + r*XS_STRIDE + c4;
        p[0] = f2tf32(v.x); p[1] = f2tf32(v.y); p[2] = f2tf32(v.z); p[3] = f2tf32(v.w);
    }
    __syncthreads();

    int w = t >> 5, lane = t & 31;
    int gid = lane >> 2, tig = lane & 3;
    int rw = (w & 3) * 32;
    int cw = (w >> 2) * 64;

    float c[2][8][4];
    #pragma unroll
    for (int rt = 0; rt < 2; rt++)
        #pragma unroll
        for (int ct = 0; ct < 8; ct++)
            c[rt][ct][0] = c[rt][ct][1] = c[rt][ct][2] = c[rt][ct][3] = 0.f;

    #pragma unroll
    for (int ks = 0; ks < 16; ks++) {
        int k0 = ks * 8;
        unsigned a[2][4], b[8][2];
        #pragma unroll
        for (int rt = 0; rt < 2; rt++) {
            int rbase = rw + rt*16;
            a[rt][0] = Xs[(rbase + gid    )*XS_STRIDE + k0 + tig];
            a[rt][1] = Xs[(rbase + gid + 8)*XS_STRIDE + k0 + tig];
            a[rt][2] = Xs[(rbase + gid    )*XS_STRIDE + k0 + tig + 4];
            a[rt][3] = Xs[(rbase + gid + 8)*XS_STRIDE + k0 + tig + 4];
        }
        #pragma unroll
        for (int ct = 0; ct < 8; ct++) {
            int col = cw + ct*8 + gid;
            b[ct][0] = Ws[(k0 + tig    )*WS_STRIDE + col];
            b[ct][1] = Ws[(k0 + tig + 4)*WS_STRIDE + col];
        }
        #pragma unroll
        for (int rt = 0; rt < 2; rt++)
            #pragma unroll
            for (int ct = 0; ct < 8; ct++) {
                asm volatile(
                    "mma.sync.aligned.m16n8k8.row.col.f32.tf32.tf32.f32 "
                    "{%0,%1,%2,%3}, {%4,%5,%6,%7}, {%8,%9}, {%0,%1,%2,%3};"
                    : "+f"(c[rt][ct][0]), "+f"(c[rt][ct][1]),
                      "+f"(c[rt][ct][2]), "+f"(c[rt][ct][3])
                    : "r"(a[rt][0]), "r"(a[rt][1]), "r"(a[rt][2]), "r"(a[rt][3]),
                      "r"(b[ct][0]), "r"(b[ct][1]));
            }
    }

    #pragma unroll
    for (int rt = 0; rt < 2; rt++) {
        #pragma unroll
        for (int ct = 0; ct < 8; ct++) {
            int r1 = row0 + rw + rt*16 + gid;
            int col = cw + ct*8 + tig*2;
            if (r1 < NN)
                *(__half2*)(g_half + (size_t)r1*DD + col) = __floats2half2_rn(c[rt][ct][0], c[rt][ct][1]);
            int r2 = r1 + 8;
            if (r2 < NN)
                *(__half2*)(g_half + (size_t)r2*DD + col) = __floats2half2_rn(c[rt][ct][2], c[rt][ct][3]);
        }
    }
}

// ---------------- fused CSR gather (R4 shape, 8-wide unroll) ----------------
__device__ __forceinline__ float4 h4tof4(uint2 r) {
    __half2 a = *(__half2*)&r.x;
    __half2 b = *(__half2*)&r.y;
    float2 fa = __half22float2(a), fb = __half22float2(b);
    return make_float4(fa.x, fa.y, fb.x, fb.y);
}

__device__ __forceinline__ void fma4(float4& acc, float w, float4 v) {
    acc.x = fmaf(w, v.x, acc.x);
    acc.y = fmaf(w, v.y, acc.y);
    acc.z = fmaf(w, v.z, acc.z);
    acc.w = fmaf(w, v.w, acc.w);
}

__global__ __launch_bounds__(256) void k_gather(const float* __restrict__ bias,
                                                const int* __restrict__ batch,
                                                int off_l) {
    int n = blockIdx.x*8 + (threadIdx.x >> 5);
    if (n >= NN) return;
    int lane = threadIdx.x & 31;

    int e0 = g_off[n];
    int e1 = g_off[n + 1];
    float di = g_dinv[n];

    uint2 sraw = *(const uint2*)(g_half + (size_t)n*DD + lane*4);
    float4 sv = h4tof4(sraw);
    float w = di * di;
    float4 acc = make_float4(w*sv.x, w*sv.y, w*sv.z, w*sv.w);

    int e = e0;
    for (; e + 8 <= e1; e += 8) {
        float2 m0 = g_meta[e];
        float2 m1 = g_meta[e+1];
        float2 m2 = g_meta[e+2];
        float2 m3 = g_meta[e+3];
        float2 m4 = g_meta[e+4];
        float2 m5 = g_meta[e+5];
        float2 m6 = g_meta[e+6];
        float2 m7 = g_meta[e+7];
        uint2 r0 = *(const uint2*)(g_half + (size_t)__float_as_int(m0.x)*DD + lane*4);
        uint2 r1 = *(const uint2*)(g_half + (size_t)__float_as_int(m1.x)*DD + lane*4);
        uint2 r2 = *(const uint2*)(g_half + (size_t)__float_as_int(m2.x)*DD + lane*4);
        uint2 r3 = *(const uint2*)(g_half + (size_t)__float_as_int(m3.x)*DD + lane*4);
        uint2 r4 = *(const uint2*)(g_half + (size_t)__float_as_int(m4.x)*DD + lane*4);
        uint2 r5 = *(const uint2*)(g_half + (size_t)__float_as_int(m5.x)*DD + lane*4);
        uint2 r6 = *(const uint2*)(g_half + (size_t)__float_as_int(m6.x)*DD + lane*4);
        uint2 r7 = *(const uint2*)(g_half + (size_t)__float_as_int(m7.x)*DD + lane*4);
        fma4(acc, m0.y, h4tof4(r0));
        fma4(acc, m1.y, h4tof4(r1));
        fma4(acc, m2.y, h4tof4(r2));
        fma4(acc, m3.y, h4tof4(r3));
        fma4(acc, m4.y, h4tof4(r4));
        fma4(acc, m5.y, h4tof4(r5));
        fma4(acc, m6.y, h4tof4(r6));
        fma4(acc, m7.y, h4tof4(r7));
    }
    for (; e + 2 <= e1; e += 2) {
        float2 m0 = g_meta[e];
        float2 m1 = g_meta[e+1];
        uint2 r0 = *(const uint2*)(g_half + (size_t)__float_as_int(m0.x)*DD + lane*4);
        uint2 r1 = *(const uint2*)(g_half + (size_t)__float_as_int(m1.x)*DD + lane*4);
        fma4(acc, m0.y, h4tof4(r0));
        fma4(acc, m1.y, h4tof4(r1));
    }
    if (e < e1) {
        float2 m0 = g_meta[e];
        uint2 r0 = *(const uint2*)(g_half + (size_t)__float_as_int(m0.x)*DD + lane*4);
        fma4(acc, m0.y, h4tof4(r0));
    }

    float4 b4 = ((const float4*)bias)[lane];
    acc.x = fmaxf(acc.x + b4.x, 0.f);
    acc.y = fmaxf(acc.y + b4.y, 0.f);
    acc.z = fmaxf(acc.z + b4.z, 0.f);
    acc.w = fmaxf(acc.w + b4.w, 0.f);

    *(float4*)(g_bufB + (size_t)n*DD + lane*4) = acc;

    int g = batch[n];
    float* q = g_pooled + g*JK + off_l + lane*4;
    asm volatile("red.global.add.v4.f32 [%0], {%1,%2,%3,%4};"
                 :: "l"(q), "f"(acc.x), "f"(acc.y), "f"(acc.z), "f"(acc.w) : "memory");
}

// ---------------- head ----------------
__global__ __launch_bounds__(128) void k_head1(const float* __restrict__ l1w,
                                               const float* __restrict__ l1b) {
    int g = blockIdx.x;
    int j = threadIdx.x;
    __shared__ float ps[JK];
    float inv = 1.f / fmaxf(g_cnt[g], 1.f);
    for (int k = j; k < JK; k += 128) ps[k] = g_pooled[g*JK + k] * inv;
    __syncthreads();
    float s = l1b[j];
    #pragma unroll 4
    for (int k = 0; k < JK; k++) s = fmaf(ps[k], l1w[k*DD + j], s);
    g_dense[g*DD + j] = fmaxf(s, 0.f);
}

__global__ __launch_bounds__(64) void k_head2(const float* __restrict__ l2w,
                                              const float* __restrict__ l2b,
                                              float* __restrict__ out) {
    __shared__ float ws[DD*10];
    __shared__ float bs[10];
    int t = threadIdx.x;
    for (int i = t; i < DD*10; i += 64) ws[i] = l2w[i];
    if (t < 10) bs[t] = l2b[t];
    __syncthreads();
    if (t < NG) {
        float z[10];
        #pragma unroll
        for (int c = 0; c < 10; c++) z[c] = bs[c];
        for (int k = 0; k < DD; k++) {
            float gv = g_dense[t*DD + k];
            #pragma unroll
            for (int c = 0; c < 10; c++) z[c] = fmaf(gv, ws[k*10 + c], z[c]);
        }
        float m = z[0];
        #pragma unroll
        for (int c = 1; c < 10; c++) m = fmaxf(m, z[c]);
        float ssum = 0.f;
        #pragma unroll
        for (int c = 0; c < 10; c++) ssum += expf(z[c] - m);
        float ls = m + logf(ssum);
        #pragma unroll
        for (int c = 0; c < 10; c++) out[t*10 + c] = z[c] - ls;
    }
}

// ---------------- launch (serial, single stream) ----------------
extern "C" void kernel_launch(void* const* d_in, const int* in_sizes, int n_in,
                              void* d_out, int out_size) {
    const float* x     = (const float*)d_in[0];
    const int*   ei    = (const int*)  d_in[1];
    const int*   batch = (const int*)  d_in[2];
    const float* W1 = (const float*)d_in[4];  const float* b1 = (const float*)d_in[5];
    const float* W2 = (const float*)d_in[6];  const float* b2 = (const float*)d_in[7];
    const float* W3 = (const float*)d_in[8];  const float* b3 = (const float*)d_in[9];
    const float* l1w = (const float*)d_in[10]; const float* l1b = (const float*)d_in[11];
    const float* l2w = (const float*)d_in[12]; const float* l2b = (const float*)d_in[13];
    float* out = (float*)d_out;

    static int once = 0;
    if (!once) {
        cudaFuncSetAttribute(k_gemm_tc, cudaFuncAttributeMaxDynamicSharedMemorySize,
                             (128*XS_STRIDE + 128*WS_STRIDE) * 4);
        once = 1;
    }

    k_init    <<<(NN + 255)/256, 256>>>();
    k_deg     <<<(NE + 255)/256, 256>>>(ei);
    k_dinv_cnt<<<(NN + 255)/256, 256>>>(batch);
    k_scan1   <<<NB_SCAN, 1024>>>();
    k_scan2   <<<1, 128>>>();
    k_scan3   <<<(NN + 255)/256, 256>>>();
    k_reorder <<<(NE + 255)/256, 256>>>(ei);

    const float* Wl[3] = {W1, W2, W3};
    const float* bl[3] = {b1, b2, b3};
    for (int l = 0; l < 3; l++) {
        k_gemm_tc<<<(NN + 127)/128, 256, (128*XS_STRIDE + 128*WS_STRIDE)*4>>>(x, Wl[l], l == 0 ? 1 : 0);
        k_gather <<<(NN + 7)/8, 256>>>(bl[l], batch, l*DD);
    }

    k_head1<<<NG, 128>>>(l1w, l1b);
    k_head2<<<1, 64>>>(l2w, l2b, out);
}

// round 10
// speedup vs baseline: 1.7916x; 1.0613x over previous
#include <cuda_runtime.h>
#include <cuda_fp16.h>
#include <math.h>

#define NN 100000
#define NE 1600000
#define DD 128
#define NG 64
#define JK (3*DD)   // 384

#define NB_SCAN 98          // ceil(NN/1024)
#define XS_STRIDE 132
#define WS_STRIDE 136

// ---------------- scratch (device globals) ----------------
__device__ float  g_dinv[NN];
__device__ int    g_deg[NN];
__device__ int    g_inc[NN];
__device__ int    g_part[NB_SCAN];
__device__ int    g_off[NN + 1];
__device__ int    g_fill[NN];
__device__ float2 g_meta[NE];                 // {src bits, norm}, dst-sorted
__device__ __half g_half[(size_t)NN*DD];      // GEMM output messages (fp16)
__device__ __half g_jk[(size_t)NN*JK];        // JK-concat layer outputs (fp16)
__device__ float  g_pooled[NG*JK];
__device__ float  g_cnt[NG];
__device__ float  g_dense[NG*DD];

// ---------------- preprocessing ----------------
__global__ void k_init() {
    int i = blockIdx.x*256 + threadIdx.x;
    if (i < NN) g_deg[i] = 0;
    if (i < NG*JK) g_pooled[i] = 0.0f;
    if (i < NG) g_cnt[i] = 0.0f;
}

__global__ void k_deg(const int* __restrict__ ei) {
    int e = blockIdx.x*256 + threadIdx.x;
    if (e < NE) atomicAdd(&g_deg[ei[NE + e]], 1);
}

__global__ void k_dinv_cnt(const int* __restrict__ batch) {
    int i = blockIdx.x*256 + threadIdx.x;
    if (i < NN) {
        g_dinv[i] = rsqrtf((float)g_deg[i] + 1.0f);
        atomicAdd(&g_cnt[batch[i]], 1.0f);
    }
}

__global__ __launch_bounds__(1024) void k_scan1() {
    __shared__ int sh[1024];
    int t = threadIdx.x;
    int i = blockIdx.x*1024 + t;
    int v = (i < NN) ? g_deg[i] : 0;
    sh[t] = v;
    __syncthreads();
    for (int off = 1; off < 1024; off <<= 1) {
        int add = (t >= off) ? sh[t - off] : 0;
        __syncthreads();
        sh[t] += add;
        __syncthreads();
    }
    if (i < NN) g_inc[i] = sh[t];
    if (t == 1023) g_part[blockIdx.x] = sh[1023];
}

// scan of block partials fused into the offset kernel.
// Each block covers 256 nodes -> one scan-block b = blockIdx.x>>2 (1024/256).
__global__ __launch_bounds__(256) void k_scan23() {
    __shared__ int sp[NB_SCAN];
    __shared__ int pref;
    int t = threadIdx.x;
    if (t < NB_SCAN) sp[t] = g_part[t];
    __syncthreads();
    int b = blockIdx.x >> 2;
    if (t == 0) {
        int run = 0;
        for (int q = 0; q < b; q++) run += sp[q];
        pref = run;
    }
    __syncthreads();
    int i = blockIdx.x*256 + t;
    if (i < NN) {
        int off = g_inc[i] - g_deg[i] + pref;
        g_off[i] = off;
        g_fill[i] = off;
    }
    if (i == 0) g_off[NN] = NE;
}

__global__ void k_reorder(const int* __restrict__ ei) {
    int e = blockIdx.x*256 + threadIdx.x;
    if (e < NE) {
        int s = ei[e];
        int d = ei[NE + e];
        int pos = atomicAdd(&g_fill[d], 1);
        float2 m;
        m.x = __int_as_float(s);
        m.y = g_dinv[s] * g_dinv[d];
        g_meta[pos] = m;
    }
}

// ---------------- tf32 tensor-core GEMM: g_half = fp16(X @ W) ----------------
// layer 0: X = external fp32 [NN,128]; layer>=1: X = g_jk fp16 rows (stride JK, col offset (layer-1)*128)
__device__ __forceinline__ unsigned f2tf32(float f) {
    unsigned u;
    asm("cvt.rna.tf32.f32 %0, %1;" : "=r"(u) : "f"(f));
    return u;
}

__global__ __launch_bounds__(256, 1) void k_gemm_tc(const float* __restrict__ Xext,
                                                    const float* __restrict__ W,
                                                    int layer) {
    extern __shared__ unsigned sh[];
    unsigned* Xs = sh;
    unsigned* Ws = sh + 128*XS_STRIDE;

    int t = threadIdx.x;
    int row0 = blockIdx.x * 128;

    for (int i = t; i < 128*32; i += 256) {
        int r = i >> 5, c4 = (i & 31) * 4;
        float4 v = *(const float4*)(W + r*128 + c4);
        unsigned* p = Ws + r*WS_STRIDE + c4;
        p[0] = f2tf32(v.x); p[1] = f2tf32(v.y); p[2] = f2tf32(v.z); p[3] = f2tf32(v.w);
    }
    if (layer == 0) {
        for (int i = t; i < 128*32; i += 256) {
            int r = i >> 5, c4 = (i & 31) * 4;
            int row = row0 + r;
            float4 v = make_float4(0.f, 0.f, 0.f, 0.f);
            if (row < NN) v = *(const float4*)(Xext + (size_t)row*DD + c4);
            unsigned* p = Xs + r*XS_STRIDE + c4;
            p[0] = f2tf32(v.x); p[1] = f2tf32(v.y); p[2] = f2tf32(v.z); p[3] = f2tf32(v.w);
        }
    } else {
        int srcoff = (layer - 1) * DD;
        for (int i = t; i < 128*32; i += 256) {
            int r = i >> 5, c4 = (i & 31) * 4;
            int row = row0 + r;
            uint2 hv = make_uint2(0u, 0u);
            if (row < NN) hv = *(const uint2*)(g_jk + (size_t)row*JK + srcoff + c4);
            float2 f0 = __half22float2(*(__half2*)&hv.x);
            float2 f1 = __half22float2(*(__half2*)&hv.y);
            unsigned* p = Xs + r*XS_STRIDE + c4;
            p[0] = f2tf32(f0.x); p[1] = f2tf32(f0.y); p[2] = f2tf32(f1.x); p[3] = f2tf32(f1.y);
        }
    }
    __syncthreads();

    int w = t >> 5, lane = t & 31;
    int gid = lane >> 2, tig = lane & 3;
    int rw = (w & 3) * 32;
    int cw = (w >> 2) * 64;

    float c[2][8][4];
    #pragma unroll
    for (int rt = 0; rt < 2; rt++)
        #pragma unroll
        for (int ct = 0; ct < 8; ct++)
            c[rt][ct][0] = c[rt][ct][1] = c[rt][ct][2] = c[rt][ct][3] = 0.f;

    #pragma unroll
    for (int ks = 0; ks < 16; ks++) {
        int k0 = ks * 8;
        unsigned a[2][4], b[8][2];
        #pragma unroll
        for (int rt = 0; rt < 2; rt++) {
            int rbase = rw + rt*16;
            a[rt][0] = Xs[(rbase + gid    )*XS_STRIDE + k0 + tig];
            a[rt][1] = Xs[(rbase + gid + 8)*XS_STRIDE + k0 + tig];
            a[rt][2] = Xs[(rbase + gid    )*XS_STRIDE + k0 + tig + 4];
            a[rt][3] = Xs[(rbase + gid + 8)*XS_STRIDE + k0 + tig + 4];
        }
        #pragma unroll
        for (int ct = 0; ct < 8; ct++) {
            int col = cw + ct*8 + gid;
            b[ct][0] = Ws[(k0 + tig    )*WS_STRIDE + col];
            b[ct][1] = Ws[(k0 + tig + 4)*WS_STRIDE + col];
        }
        #pragma unroll
        for (int rt = 0; rt < 2; rt++)
            #pragma unroll
            for (int ct = 0; ct < 8; ct++) {
                asm volatile(
                    "mma.sync.aligned.m16n8k8.row.col.f32.tf32.tf32.f32 "
                    "{%0,%1,%2,%3}, {%4,%5,%6,%7}, {%8,%9}, {%0,%1,%2,%3};"
                    : "+f"(c[rt][ct][0]), "+f"(c[rt][ct][1]),
                      "+f"(c[rt][ct][2]), "+f"(c[rt][ct][3])
                    : "r"(a[rt][0]), "r"(a[rt][1]), "r"(a[rt][2]), "r"(a[rt][3]),
                      "r"(b[ct][0]), "r"(b[ct][1]));
            }
    }

    #pragma unroll
    for (int rt = 0; rt < 2; rt++) {
        #pragma unroll
        for (int ct = 0; ct < 8; ct++) {
            int r1 = row0 + rw + rt*16 + gid;
            int col = cw + ct*8 + tig*2;
            if (r1 < NN)
                *(__half2*)(g_half + (size_t)r1*DD + col) = __floats2half2_rn(c[rt][ct][0], c[rt][ct][1]);
            int r2 = r1 + 8;
            if (r2 < NN)
                *(__half2*)(g_half + (size_t)r2*DD + col) = __floats2half2_rn(c[rt][ct][2], c[rt][ct][3]);
        }
    }
}

// ---------------- fused CSR gather (one node/warp, 8-wide unroll, fp16 out) ----------------
__device__ __forceinline__ float4 h4tof4(uint2 r) {
    __half2 a = *(__half2*)&r.x;
    __half2 b = *(__half2*)&r.y;
    float2 fa = __half22float2(a), fb = __half22float2(b);
    return make_float4(fa.x, fa.y, fb.x, fb.y);
}

__device__ __forceinline__ void fma4(float4& acc, float w, float4 v) {
    acc.x = fmaf(w, v.x, acc.x);
    acc.y = fmaf(w, v.y, acc.y);
    acc.z = fmaf(w, v.z, acc.z);
    acc.w = fmaf(w, v.w, acc.w);
}

__global__ __launch_bounds__(256) void k_gather(const float* __restrict__ bias,
                                                const int* __restrict__ batch,
                                                int off_l) {
    int n = blockIdx.x*8 + (threadIdx.x >> 5);
    if (n >= NN) return;
    int lane = threadIdx.x & 31;

    int e0 = g_off[n];
    int e1 = g_off[n + 1];
    float di = g_dinv[n];

    uint2 sraw = *(const uint2*)(g_half + (size_t)n*DD + lane*4);
    float4 sv = h4tof4(sraw);
    float w = di * di;
    float4 acc = make_float4(w*sv.x, w*sv.y, w*sv.z, w*sv.w);

    int e = e0;
    for (; e + 8 <= e1; e += 8) {
        float2 m0 = g_meta[e];
        float2 m1 = g_meta[e+1];
        float2 m2 = g_meta[e+2];
        float2 m3 = g_meta[e+3];
        float2 m4 = g_meta[e+4];
        float2 m5 = g_meta[e+5];
        float2 m6 = g_meta[e+6];
        float2 m7 = g_meta[e+7];
        uint2 r0 = *(const uint2*)(g_half + (size_t)__float_as_int(m0.x)*DD + lane*4);
        uint2 r1 = *(const uint2*)(g_half + (size_t)__float_as_int(m1.x)*DD + lane*4);
        uint2 r2 = *(const uint2*)(g_half + (size_t)__float_as_int(m2.x)*DD + lane*4);
        uint2 r3 = *(const uint2*)(g_half + (size_t)__float_as_int(m3.x)*DD + lane*4);
        uint2 r4 = *(const uint2*)(g_half + (size_t)__float_as_int(m4.x)*DD + lane*4);
        uint2 r5 = *(const uint2*)(g_half + (size_t)__float_as_int(m5.x)*DD + lane*4);
        uint2 r6 = *(const uint2*)(g_half + (size_t)__float_as_int(m6.x)*DD + lane*4);
        uint2 r7 = *(const uint2*)(g_half + (size_t)__float_as_int(m7.x)*DD + lane*4);
        fma4(acc, m0.y, h4tof4(r0));
        fma4(acc, m1.y, h4tof4(r1));
        fma4(acc, m2.y, h4tof4(r2));
        fma4(acc, m3.y, h4tof4(r3));
        fma4(acc, m4.y, h4tof4(r4));
        fma4(acc, m5.y, h4tof4(r5));
        fma4(acc, m6.y, h4tof4(r6));
        fma4(acc, m7.y, h4tof4(r7));
    }
    for (; e + 2 <= e1; e += 2) {
        float2 m0 = g_meta[e];
        float2 m1 = g_meta[e+1];
        uint2 r0 = *(const uint2*)(g_half + (size_t)__float_as_int(m0.x)*DD + lane*4);
        uint2 r1 = *(const uint2*)(g_half + (size_t)__float_as_int(m1.x)*DD + lane*4);
        fma4(acc, m0.y, h4tof4(r0));
        fma4(acc, m1.y, h4tof4(r1));
    }
    if (e < e1) {
        float2 m0 = g_meta[e];
        uint2 r0 = *(const uint2*)(g_half + (size_t)__float_as_int(m0.x)*DD + lane*4);
        fma4(acc, m0.y, h4tof4(r0));
    }

    float4 b4 = ((const float4*)bias)[lane];
    acc.x = fmaxf(acc.x + b4.x, 0.f);
    acc.y = fmaxf(acc.y + b4.y, 0.f);
    acc.z = fmaxf(acc.z + b4.z, 0.f);
    acc.w = fmaxf(acc.w + b4.w, 0.f);

    // store fp16 into JK-concat buffer
    uint2 hv;
    *(__half2*)&hv.x = __floats2half2_rn(acc.x, acc.y);
    *(__half2*)&hv.y = __floats2half2_rn(acc.z, acc.w);
    *(uint2*)(g_jk + (size_t)n*JK + off_l + lane*4) = hv;

    int g = batch[n];
    float* q = g_pooled + g*JK + off_l + lane*4;
    asm volatile("red.global.add.v4.f32 [%0], {%1,%2,%3,%4};"
                 :: "l"(q), "f"(acc.x), "f"(acc.y), "f"(acc.z), "f"(acc.w) : "memory");
}

// ---------------- head ----------------
__global__ __launch_bounds__(128) void k_head1(const float* __restrict__ l1w,
                                               const float* __restrict__ l1b) {
    int g = blockIdx.x;
    int j = threadIdx.x;
    __shared__ float ps[JK];
    float inv = 1.f / fmaxf(g_cnt[g], 1.f);
    for (int k = j; k < JK; k += 128) ps[k] = g_pooled[g*JK + k] * inv;
    __syncthreads();
    float s = l1b[j];
    #pragma unroll 4
    for (int k = 0; k < JK; k++) s = fmaf(ps[k], l1w[k*DD + j], s);
    g_dense[g*DD + j] = fmaxf(s, 0.f);
}

__global__ __launch_bounds__(64) void k_head2(const float* __restrict__ l2w,
                                              const float* __restrict__ l2b,
                                              float* __restrict__ out) {
    __shared__ float ws[DD*10];
    __shared__ float bs[10];
    int t = threadIdx.x;
    for (int i = t; i < DD*10; i += 64) ws[i] = l2w[i];
    if (t < 10) bs[t] = l2b[t];
    __syncthreads();
    if (t < NG) {
        float z[10];
        #pragma unroll
        for (int c = 0; c < 10; c++) z[c] = bs[c];
        for (int k = 0; k < DD; k++) {
            float gv = g_dense[t*DD + k];
            #pragma unroll
            for (int c = 0; c < 10; c++) z[c] = fmaf(gv, ws[k*10 + c], z[c]);
        }
        float m = z[0];
        #pragma unroll
        for (int c = 1; c < 10; c++) m = fmaxf(m, z[c]);
        float ssum = 0.f;
        #pragma unroll
        for (int c = 0; c < 10; c++) ssum += expf(z[c] - m);
        float ls = m + logf(ssum);
        #pragma unroll
        for (int c = 0; c < 10; c++) out[t*10 + c] = z[c] - ls;
    }
}

// ---------------- launch (serial; gemm1 placed 4th for ncu) ----------------
extern "C" void kernel_launch(void* const* d_in, const int* in_sizes, int n_in,
                              void* d_out, int out_size) {
    const float* x     = (const float*)d_in[0];
    const int*   ei    = (const int*)  d_in[1];
    const int*   batch = (const int*)  d_in[2];
    const float* W1 = (const float*)d_in[4];  const float* b1 = (const float*)d_in[5];
    const float* W2 = (const float*)d_in[6];  const float* b2 = (const float*)d_in[7];
    const float* W3 = (const float*)d_in[8];  const float* b3 = (const float*)d_in[9];
    const float* l1w = (const float*)d_in[10]; const float* l1b = (const float*)d_in[11];
    const float* l2w = (const float*)d_in[12]; const float* l2b = (const float*)d_in[13];
    float* out = (float*)d_out;

    static int once = 0;
    if (!once) {
        cudaFuncSetAttribute(k_gemm_tc, cudaFuncAttributeMaxDynamicSharedMemorySize,
                             (128*XS_STRIDE + 128*WS_STRIDE) * 4);
        once = 1;
    }

    k_init    <<<(NN + 255)/256, 256>>>();                                   // 1
    k_deg     <<<(NE + 255)/256, 256>>>(ei);                                 // 2
    k_dinv_cnt<<<(NN + 255)/256, 256>>>(batch);                              // 3
    k_gemm_tc <<<(NN + 127)/128, 256, (128*XS_STRIDE + 128*WS_STRIDE)*4>>>(x, W1, 0);  // 4 (profiled)
    k_scan1   <<<NB_SCAN, 1024>>>();                                         // 5
    k_scan23  <<<(NN + 255)/256, 256>>>();                                   // 6
    k_reorder <<<(NE + 255)/256, 256>>>(ei);                                 // 7

    k_gather  <<<(NN + 7)/8, 256>>>(b1, batch, 0*DD);
    k_gemm_tc <<<(NN + 127)/128, 256, (128*XS_STRIDE + 128*WS_STRIDE)*4>>>(x, W2, 1);
    k_gather  <<<(NN + 7)/8, 256>>>(b2, batch, 1*DD);
    k_gemm_tc <<<(NN + 127)/128, 256, (128*XS_STRIDE + 128*WS_STRIDE)*4>>>(x, W3, 2);
    k_gather  <<<(NN + 7)/8, 256>>>(b3, batch, 2*DD);

    k_head1<<<NG, 128>>>(l1w, l1b);
    k_head2<<<1, 64>>>(l2w, l2b, out);
}

// round 12
// speedup vs baseline: 1.9438x; 1.0850x over previous
#include <cuda_runtime.h>
#include <cuda_fp16.h>
#include <math.h>

#define NN 100000
#define NE 1600000
#define DD 128
#define NG 64
#define JK (3*DD)   // 384

#define NB_SCAN 98          // ceil(NN/1024)
#define XSH 136             // smem row stride in halves (272B -> conflict-free)
#define XSH2 (XSH/2)        // 68, stride in half2

// ---------------- scratch (device globals) ----------------
__device__ float  g_dinv[NN];
__device__ int    g_deg[NN];
__device__ int    g_inc[NN];
__device__ int    g_part[NB_SCAN];
__device__ int    g_off[NN + 1];
__device__ int    g_fill[NN];
__device__ float2 g_meta[NE];                 // {src bits, norm}, dst-sorted
__device__ __half g_half[(size_t)NN*DD];      // GEMM output messages (fp16)
__device__ __half g_jk[(size_t)NN*JK];        // JK-concat layer outputs (fp16)
__device__ float  g_pooled[NG*JK];
__device__ float  g_cnt[NG];
__device__ float  g_dense[NG*DD];

// ---------------- preprocessing ----------------
__global__ void k_init() {
    int i = blockIdx.x*256 + threadIdx.x;
    if (i < NN) g_deg[i] = 0;
    if (i < NG*JK) g_pooled[i] = 0.0f;
    if (i < NG) g_cnt[i] = 0.0f;
}

__global__ void k_deg(const int* __restrict__ ei) {
    int e = blockIdx.x*256 + threadIdx.x;
    if (e < NE) atomicAdd(&g_deg[ei[NE + e]], 1);
}

__global__ void k_dinv_cnt(const int* __restrict__ batch) {
    int i = blockIdx.x*256 + threadIdx.x;
    if (i < NN) {
        g_dinv[i] = rsqrtf((float)g_deg[i] + 1.0f);
        atomicAdd(&g_cnt[batch[i]], 1.0f);
    }
}

__global__ __launch_bounds__(1024) void k_scan1() {
    __shared__ int sh[1024];
    int t = threadIdx.x;
    int i = blockIdx.x*1024 + t;
    int v = (i < NN) ? g_deg[i] : 0;
    sh[t] = v;
    __syncthreads();
    for (int off = 1; off < 1024; off <<= 1) {
        int add = (t >= off) ? sh[t - off] : 0;
        __syncthreads();
        sh[t] += add;
        __syncthreads();
    }
    if (i < NN) g_inc[i] = sh[t];
    if (t == 1023) g_part[blockIdx.x] = sh[1023];
}

// fused partial-scan + offsets (each 256-node block has uniform scan-block id)
__global__ __launch_bounds__(256) void k_scan23() {
    __shared__ int sp[NB_SCAN];
    __shared__ int pref;
    int t = threadIdx.x;
    if (t < NB_SCAN) sp[t] = g_part[t];
    __syncthreads();
    int b = blockIdx.x >> 2;
    if (t == 0) {
        int run = 0;
        for (int q = 0; q < b; q++) run += sp[q];
        pref = run;
    }
    __syncthreads();
    int i = blockIdx.x*256 + t;
    if (i < NN) {
        int off = g_inc[i] - g_deg[i] + pref;
        g_off[i] = off;
        g_fill[i] = off;
    }
    if (i == 0) g_off[NN] = NE;
}

__global__ void k_reorder(const int* __restrict__ ei) {
    int e = blockIdx.x*256 + threadIdx.x;
    if (e < NE) {
        int s = ei[e];
        int d = ei[NE + e];
        int pos = atomicAdd(&g_fill[d], 1);
        float2 m;
        m.x = __int_as_float(s);
        m.y = g_dinv[s] * g_dinv[d];
        g_meta[pos] = m;
    }
}

// ---------------- fp16 tensor-core GEMM: g_half = fp16(X @ W) ----------------
// layer 0: X = external fp32 [NN,128]; layer>=1: X = g_jk fp16 rows (stride JK, col off (layer-1)*128)
__global__ __launch_bounds__(256, 3) void k_gemm_tc(const float* __restrict__ Xext,
                                                    const float* __restrict__ W,
                                                    int layer) {
    extern __shared__ __half sh[];
    __half* Xs = sh;                    // 128 x XSH halves
    __half* Ws = sh + 128*XSH;          // W transposed: [n][k], 128 x XSH halves

    int t = threadIdx.x;
    int row0 = blockIdx.x * 128;

    // load W [k][n] fp32 -> smem transposed [n][k] fp16
    for (int i = t; i < 128*32; i += 256) {
        int k = i >> 5, n4 = (i & 31) * 4;
        float4 v = *(const float4*)(W + k*128 + n4);
        Ws[(n4 + 0)*XSH + k] = __float2half_rn(v.x);
        Ws[(n4 + 1)*XSH + k] = __float2half_rn(v.y);
        Ws[(n4 + 2)*XSH + k] = __float2half_rn(v.z);
        Ws[(n4 + 3)*XSH + k] = __float2half_rn(v.w);
    }
    // load X tile [128 rows][128 cols] fp16 row-major
    if (layer == 0) {
        for (int i = t; i < 128*32; i += 256) {
            int r = i >> 5, c4 = (i & 31) * 4;
            int row = row0 + r;
            float4 v = make_float4(0.f, 0.f, 0.f, 0.f);
            if (row < NN) v = *(const float4*)(Xext + (size_t)row*DD + c4);
            __half2* p = (__half2*)(Xs + r*XSH + c4);
            p[0] = __floats2half2_rn(v.x, v.y);
            p[1] = __floats2half2_rn(v.z, v.w);
        }
    } else {
        int srcoff = (layer - 1) * DD;
        for (int i = t; i < 128*32; i += 256) {
            int r = i >> 5, c4 = (i & 31) * 4;
            int row = row0 + r;
            uint2 hv = make_uint2(0u, 0u);
            if (row < NN) hv = *(const uint2*)(g_jk + (size_t)row*JK + srcoff + c4);
            *(uint2*)(Xs + r*XSH + c4) = hv;
        }
    }
    __syncthreads();

    int w = t >> 5, lane = t & 31;
    int gid = lane >> 2, tig = lane & 3;
    int rw = (w & 3) * 32;     // warp row base
    int cw = (w >> 2) * 64;    // warp col base

    float c[2][8][4];
    #pragma unroll
    for (int rt = 0; rt < 2; rt++)
        #pragma unroll
        for (int ct = 0; ct < 8; ct++)
            c[rt][ct][0] = c[rt][ct][1] = c[rt][ct][2] = c[rt][ct][3] = 0.f;

    const unsigned* Xh2 = (const unsigned*)Xs;
    const unsigned* Wh2 = (const unsigned*)Ws;

    #pragma unroll
    for (int ks = 0; ks < 8; ks++) {
        int kh = ks*8 + tig;            // half2 index within row (k0 = ks*16)
        unsigned a[2][4], b[8][2];
        #pragma unroll
        for (int rt = 0; rt < 2; rt++) {
            int rbase = rw + rt*16;
            a[rt][0] = Xh2[(rbase + gid    )*XSH2 + kh];
            a[rt][1] = Xh2[(rbase + gid + 8)*XSH2 + kh];
            a[rt][2] = Xh2[(rbase + gid    )*XSH2 + kh + 4];
            a[rt][3] = Xh2[(rbase + gid + 8)*XSH2 + kh + 4];
        }
        #pragma unroll
        for (int ct = 0; ct < 8; ct++) {
            int col = cw + ct*8 + gid;
            b[ct][0] = Wh2[col*XSH2 + kh];
            b[ct][1] = Wh2[col*XSH2 + kh + 4];
        }
        #pragma unroll
        for (int rt = 0; rt < 2; rt++)
            #pragma unroll
            for (int ct = 0; ct < 8; ct++) {
                asm volatile(
                    "mma.sync.aligned.m16n8k16.row.col.f32.f16.f16.f32 "
                    "{%0,%1,%2,%3}, {%4,%5,%6,%7}, {%8,%9}, {%0,%1,%2,%3};"
                    : "+f"(c[rt][ct][0]), "+f"(c[rt][ct][1]),
                      "+f"(c[rt][ct][2]), "+f"(c[rt][ct][3])
                    : "r"(a[rt][0]), "r"(a[rt][1]), "r"(a[rt][2]), "r"(a[rt][3]),
                      "r"(b[ct][0]), "r"(b[ct][1]));
            }
    }

    // store C as fp16 messages
    #pragma unroll
    for (int rt = 0; rt < 2; rt++) {
        #pragma unroll
        for (int ct = 0; ct < 8; ct++) {
            int r1 = row0 + rw + rt*16 + gid;
            int col = cw + ct*8 + tig*2;
            if (r1 < NN)
                *(__half2*)(g_half + (size_t)r1*DD + col) = __floats2half2_rn(c[rt][ct][0], c[rt][ct][1]);
            int r2 = r1 + 8;
            if (r2 < NN)
                *(__half2*)(g_half + (size_t)r2*DD + col) = __floats2half2_rn(c[rt][ct][2], c[rt][ct][3]);
        }
    }
}

// ---------------- fused CSR gather (one node/warp, 8-wide unroll, fp16 out) ----------------
__device__ __forceinline__ float4 h4tof4(uint2 r) {
    __half2 a = *(__half2*)&r.x;
    __half2 b = *(__half2*)&r.y;
    float2 fa = __half22float2(a), fb = __half22float2(b);
    return make_float4(fa.x, fa.y, fb.x, fb.y);
}

__device__ __forceinline__ void fma4(float4& acc, float w, float4 v) {
    acc.x = fmaf(w, v.x, acc.x);
    acc.y = fmaf(w, v.y, acc.y);
    acc.z = fmaf(w, v.z, acc.z);
    acc.w = fmaf(w, v.w, acc.w);
}

__global__ __launch_bounds__(256) void k_gather(const float* __restrict__ bias,
                                                const int* __restrict__ batch,
                                                int off_l) {
    int n = blockIdx.x*8 + (threadIdx.x >> 5);
    if (n >= NN) return;
    int lane = threadIdx.x & 31;

    int e0 = g_off[n];
    int e1 = g_off[n + 1];
    float di = g_dinv[n];

    uint2 sraw = *(const uint2*)(g_half + (size_t)n*DD + lane*4);
    float4 sv = h4tof4(sraw);
    float w = di * di;
    float4 acc = make_float4(w*sv.x, w*sv.y, w*sv.z, w*sv.w);

    int e = e0;
    for (; e + 8 <= e1; e += 8) {
        float2 m0 = g_meta[e];
        float2 m1 = g_meta[e+1];
        float2 m2 = g_meta[e+2];
        float2 m3 = g_meta[e+3];
        float2 m4 = g_meta[e+4];
        float2 m5 = g_meta[e+5];
        float2 m6 = g_meta[e+6];
        float2 m7 = g_meta[e+7];
        uint2 r0 = *(const uint2*)(g_half + (size_t)__float_as_int(m0.x)*DD + lane*4);
        uint2 r1 = *(const uint2*)(g_half + (size_t)__float_as_int(m1.x)*DD + lane*4);
        uint2 r2 = *(const uint2*)(g_half + (size_t)__float_as_int(m2.x)*DD + lane*4);
        uint2 r3 = *(const uint2*)(g_half + (size_t)__float_as_int(m3.x)*DD + lane*4);
        uint2 r4 = *(const uint2*)(g_half + (size_t)__float_as_int(m4.x)*DD + lane*4);
        uint2 r5 = *(const uint2*)(g_half + (size_t)__float_as_int(m5.x)*DD + lane*4);
        uint2 r6 = *(const uint2*)(g_half + (size_t)__float_as_int(m6.x)*DD + lane*4);
        uint2 r7 = *(const uint2*)(g_half + (size_t)__float_as_int(m7.x)*DD + lane*4);
        fma4(acc, m0.y, h4tof4(r0));
        fma4(acc, m1.y, h4tof4(r1));
        fma4(acc, m2.y, h4tof4(r2));
        fma4(acc, m3.y, h4tof4(r3));
        fma4(acc, m4.y, h4tof4(r4));
        fma4(acc, m5.y, h4tof4(r5));
        fma4(acc, m6.y, h4tof4(r6));
        fma4(acc, m7.y, h4tof4(r7));
    }
    for (; e + 2 <= e1; e += 2) {
        float2 m0 = g_meta[e];
        float2 m1 = g_meta[e+1];
        uint2 r0 = *(const uint2*)(g_half + (size_t)__float_as_int(m0.x)*DD + lane*4);
        uint2 r1 = *(const uint2*)(g_half + (size_t)__float_as_int(m1.x)*DD + lane*4);
        fma4(acc, m0.y, h4tof4(r0));
        fma4(acc, m1.y, h4tof4(r1));
    }
    if (e < e1) {
        float2 m0 = g_meta[e];
        uint2 r0 = *(const uint2*)(g_half + (size_t)__float_as_int(m0.x)*DD + lane*4);
        fma4(acc, m0.y, h4tof4(r0));
    }

    float4 b4 = ((const float4*)bias)[lane];
    acc.x = fmaxf(acc.x + b4.x, 0.f);
    acc.y = fmaxf(acc.y + b4.y, 0.f);
    acc.z = fmaxf(acc.z + b4.z, 0.f);
    acc.w = fmaxf(acc.w + b4.w, 0.f);

    uint2 hv;
    *(__half2*)&hv.x = __floats2half2_rn(acc.x, acc.y);
    *(__half2*)&hv.y = __floats2half2_rn(acc.z, acc.w);
    *(uint2*)(g_jk + (size_t)n*JK + off_l + lane*4) = hv;

    int g = batch[n];
    float* q = g_pooled + g*JK + off_l + lane*4;
    asm volatile("red.global.add.v4.f32 [%0], {%1,%2,%3,%4};"
                 :: "l"(q), "f"(acc.x), "f"(acc.y), "f"(acc.z), "f"(acc.w) : "memory");
}

// ---------------- head ----------------
__global__ __launch_bounds__(128) void k_head1(const float* __restrict__ l1w,
                                               const float* __restrict__ l1b) {
    int g = blockIdx.x;
    int j = threadIdx.x;
    __shared__ float ps[JK];
    float inv = 1.f / fmaxf(g_cnt[g], 1.f);
    for (int k = j; k < JK; k += 128) ps[k] = g_pooled[g*JK + k] * inv;
    __syncthreads();
    float s = l1b[j];
    #pragma unroll 4
    for (int k = 0; k < JK; k++) s = fmaf(ps[k], l1w[k*DD + j], s);
    g_dense[g*DD + j] = fmaxf(s, 0.f);
}

__global__ __launch_bounds__(64) void k_head2(const float* __restrict__ l2w,
                                              const float* __restrict__ l2b,
                                              float* __restrict__ out) {
    __shared__ float ws[DD*10];
    __shared__ float bs[10];
    int t = threadIdx.x;
    for (int i = t; i < DD*10; i += 64) ws[i] = l2w[i];
    if (t < 10) bs[t] = l2b[t];
    __syncthreads();
    if (t < NG) {
        float z[10];
        #pragma unroll
        for (int c = 0; c < 10; c++) z[c] = bs[c];
        for (int k = 0; k < DD; k++) {
            float gv = g_dense[t*DD + k];
            #pragma unroll
            for (int c = 0; c < 10; c++) z[c] = fmaf(gv, ws[k*10 + c], z[c]);
        }
        float m = z[0];
        #pragma unroll
        for (int c = 1; c < 10; c++) m = fmaxf(m, z[c]);
        float ssum = 0.f;
        #pragma unroll
        for (int c = 0; c < 10; c++) ssum += expf(z[c] - m);
        float ls = m + logf(ssum);
        #pragma unroll
        for (int c = 0; c < 10; c++) out[t*10 + c] = z[c] - ls;
    }
}

// ---------------- launch (serial; gemm1 placed 4th for ncu) ----------------
#define GEMM_SMEM (2*128*XSH*2)   // 69632 bytes

extern "C" void kernel_launch(void* const* d_in, const int* in_sizes, int n_in,
                              void* d_out, int out_size) {
    const float* x     = (const float*)d_in[0];
    const int*   ei    = (const int*)  d_in[1];
    const int*   batch = (const int*)  d_in[2];
    const float* W1 = (const float*)d_in[4];  const float* b1 = (const float*)d_in[5];
    const float* W2 = (const float*)d_in[6];  const float* b2 = (const float*)d_in[7];
    const float* W3 = (const float*)d_in[8];  const float* b3 = (const float*)d_in[9];
    const float* l1w = (const float*)d_in[10]; const float* l1b = (const float*)d_in[11];
    const float* l2w = (const float*)d_in[12]; const float* l2b = (const float*)d_in[13];
    float* out = (float*)d_out;

    static int once = 0;
    if (!once) {
        cudaFuncSetAttribute(k_gemm_tc, cudaFuncAttributeMaxDynamicSharedMemorySize, GEMM_SMEM);
        once = 1;
    }

    k_init    <<<(NN + 255)/256, 256>>>();                                   // 1
    k_deg     <<<(NE + 255)/256, 256>>>(ei);                                 // 2
    k_dinv_cnt<<<(NN + 255)/256, 256>>>(batch);                              // 3
    k_gemm_tc <<<(NN + 127)/128, 256, GEMM_SMEM>>>(x, W1, 0);                // 4 (profiled)
    k_scan1   <<<NB_SCAN, 1024>>>();                                         // 5
    k_scan23  <<<(NN + 255)/256, 256>>>();                                   // 6
    k_reorder <<<(NE + 255)/256, 256>>>(ei);                                 // 7

    k_gather  <<<(NN + 7)/8, 256>>>(b1, batch, 0*DD);
    k_gemm_tc <<<(NN + 127)/128, 256, GEMM_SMEM>>>(x, W2, 1);
    k_gather  <<<(NN + 7)/8, 256>>>(b2, batch, 1*DD);
    k_gemm_tc <<<(NN + 127)/128, 256, GEMM_SMEM>>>(x, W3, 2);
    k_gather  <<<(NN + 7)/8, 256>>>(b3, batch, 2*DD);

    k_head1<<<NG, 128>>>(l1w, l1b);
    k_head2<<<1, 64>>>(l2w, l2b, out);
}

// round 13
// speedup vs baseline: 2.1511x; 1.1067x over previous
#include <cuda_runtime.h>
#include <cuda_fp16.h>
#include <math.h>

#define NN 100000
#define NE 1600000
#define DD 128
#define NG 64
#define JK (3*DD)   // 384

#define NB_SCAN 98          // ceil(NN/1024)
#define XSH 136             // smem row stride in halves (272B -> LDSM conflict-free)

// ---------------- scratch (device globals) ----------------
__device__ float  g_dinv[NN];
__device__ int    g_deg[NN];
__device__ int    g_inc[NN];
__device__ int    g_part[NB_SCAN];
__device__ int    g_off[NN + 1];
__device__ int    g_fill[NN];
__device__ float2 g_meta[NE];                 // {src bits, norm}, dst-sorted
__device__ __half g_half[(size_t)NN*DD];      // GEMM output messages (fp16)
__device__ __half g_jk[(size_t)NN*JK];        // JK-concat layer outputs (fp16)
__device__ float  g_pooled[NG*JK];
__device__ float  g_cnt[NG];
__device__ float  g_dense[NG*DD];

// ---------------- preprocessing ----------------
__global__ void k_init() {
    int i = blockIdx.x*256 + threadIdx.x;
    if (i < NN) g_deg[i] = 0;
    if (i < NG*JK) g_pooled[i] = 0.0f;
    if (i < NG) g_cnt[i] = 0.0f;
}

__global__ void k_deg(const int* __restrict__ ei) {
    int e = blockIdx.x*256 + threadIdx.x;
    if (e < NE) atomicAdd(&g_deg[ei[NE + e]], 1);
}

__global__ void k_dinv_cnt(const int* __restrict__ batch) {
    int i = blockIdx.x*256 + threadIdx.x;
    if (i < NN) {
        g_dinv[i] = rsqrtf((float)g_deg[i] + 1.0f);
        atomicAdd(&g_cnt[batch[i]], 1.0f);
    }
}

__global__ __launch_bounds__(1024) void k_scan1() {
    __shared__ int sh[1024];
    int t = threadIdx.x;
    int i = blockIdx.x*1024 + t;
    int v = (i < NN) ? g_deg[i] : 0;
    sh[t] = v;
    __syncthreads();
    for (int off = 1; off < 1024; off <<= 1) {
        int add = (t >= off) ? sh[t - off] : 0;
        __syncthreads();
        sh[t] += add;
        __syncthreads();
    }
    if (i < NN) g_inc[i] = sh[t];
    if (t == 1023) g_part[blockIdx.x] = sh[1023];
}

__global__ __launch_bounds__(256) void k_scan23() {
    __shared__ int sp[NB_SCAN];
    __shared__ int pref;
    int t = threadIdx.x;
    if (t < NB_SCAN) sp[t] = g_part[t];
    __syncthreads();
    int b = blockIdx.x >> 2;
    if (t == 0) {
        int run = 0;
        for (int q = 0; q < b; q++) run += sp[q];
        pref = run;
    }
    __syncthreads();
    int i = blockIdx.x*256 + t;
    if (i < NN) {
        int off = g_inc[i] - g_deg[i] + pref;
        g_off[i] = off;
        g_fill[i] = off;
    }
    if (i == 0) g_off[NN] = NE;
}

__global__ void k_reorder(const int* __restrict__ ei) {
    int e = blockIdx.x*256 + threadIdx.x;
    if (e < NE) {
        int s = ei[e];
        int d = ei[NE + e];
        int pos = atomicAdd(&g_fill[d], 1);
        float2 m;
        m.x = __int_as_float(s);
        m.y = g_dinv[s] * g_dinv[d];
        g_meta[pos] = m;
    }
}

// ---------------- fp16 tensor-core GEMM with LDSM fragment loads ----------------
// layer 0: X = external fp32 [NN,128]; layer>=1: X = g_jk fp16 rows (stride JK, col off (layer-1)*128)
__global__ __launch_bounds__(256, 3) void k_gemm_tc(const float* __restrict__ Xext,
                                                    const float* __restrict__ W,
                                                    int layer) {
    extern __shared__ __half sh[];
    __half* Xs = sh;                    // X tile [r][k], 128 x XSH halves
    __half* Ws = sh + 128*XSH;          // W [k][n] row-major, 128 x XSH halves

    int t = threadIdx.x;
    int row0 = blockIdx.x * 128;

    // W [k][n] fp32 -> fp16 same layout (coalesced)
    for (int i = t; i < 128*32; i += 256) {
        int k = i >> 5, n4 = (i & 31) * 4;
        float4 v = *(const float4*)(W + k*128 + n4);
        __half2* p = (__half2*)(Ws + k*XSH + n4);
        p[0] = __floats2half2_rn(v.x, v.y);
        p[1] = __floats2half2_rn(v.z, v.w);
    }
    // X tile [128 rows][128 cols] fp16 row-major
    if (layer == 0) {
        for (int i = t; i < 128*32; i += 256) {
            int r = i >> 5, c4 = (i & 31) * 4;
            int row = row0 + r;
            float4 v = make_float4(0.f, 0.f, 0.f, 0.f);
            if (row < NN) v = *(const float4*)(Xext + (size_t)row*DD + c4);
            __half2* p = (__half2*)(Xs + r*XSH + c4);
            p[0] = __floats2half2_rn(v.x, v.y);
            p[1] = __floats2half2_rn(v.z, v.w);
        }
    } else {
        int srcoff = (layer - 1) * DD;
        for (int i = t; i < 128*32; i += 256) {
            int r = i >> 5, c4 = (i & 31) * 4;
            int row = row0 + r;
            uint2 hv = make_uint2(0u, 0u);
            if (row < NN) hv = *(const uint2*)(g_jk + (size_t)row*JK + srcoff + c4);
            *(uint2*)(Xs + r*XSH + c4) = hv;
        }
    }
    __syncthreads();

    int w = t >> 5, lane = t & 31;
    int gid = lane >> 2, tig = lane & 3;
    int rw = (w & 3) * 32;     // warp row base
    int cw = (w >> 2) * 64;    // warp col base
    int l15 = lane & 15;
    int lhi = (lane >> 4) * 8;

    unsigned XsAddr = (unsigned)__cvta_generic_to_shared(Xs);
    unsigned WsAddr = (unsigned)__cvta_generic_to_shared(Ws);
    // A: row = rw + rt*16 + (lane&15), col = k0 + (lane>>4)*8
    unsigned aAddr0 = XsAddr + (unsigned)(((rw + l15)*XSH + lhi) * 2);
    // B(trans): row = k0 + (lane&15), col = cw + pr*16 + (lane>>4)*8
    unsigned bAddr0 = WsAddr + (unsigned)((l15*XSH + cw + lhi) * 2);

    float c[2][8][4];
    #pragma unroll
    for (int rt = 0; rt < 2; rt++)
        #pragma unroll
        for (int ct = 0; ct < 8; ct++)
            c[rt][ct][0] = c[rt][ct][1] = c[rt][ct][2] = c[rt][ct][3] = 0.f;

    #pragma unroll
    for (int ks = 0; ks < 8; ks++) {
        unsigned a[2][4], b[8][2];
        #pragma unroll
        for (int rt = 0; rt < 2; rt++) {
            unsigned ad = aAddr0 + rt*(16*XSH*2) + ks*32;
            asm volatile("ldmatrix.sync.aligned.m8n8.x4.shared.b16 {%0,%1,%2,%3}, [%4];"
                         : "=r"(a[rt][0]), "=r"(a[rt][1]), "=r"(a[rt][2]), "=r"(a[rt][3])
                         : "r"(ad));
        }
        #pragma unroll
        for (int pr = 0; pr < 4; pr++) {
            unsigned bd = bAddr0 + ks*(16*XSH*2) + pr*32;
            asm volatile("ldmatrix.sync.aligned.m8n8.x4.trans.shared.b16 {%0,%1,%2,%3}, [%4];"
                         : "=r"(b[2*pr][0]), "=r"(b[2*pr][1]), "=r"(b[2*pr+1][0]), "=r"(b[2*pr+1][1])
                         : "r"(bd));
        }
        #pragma unroll
        for (int rt = 0; rt < 2; rt++)
            #pragma unroll
            for (int ct = 0; ct < 8; ct++) {
                asm volatile(
                    "mma.sync.aligned.m16n8k16.row.col.f32.f16.f16.f32 "
                    "{%0,%1,%2,%3}, {%4,%5,%6,%7}, {%8,%9}, {%0,%1,%2,%3};"
                    : "+f"(c[rt][ct][0]), "+f"(c[rt][ct][1]),
                      "+f"(c[rt][ct][2]), "+f"(c[rt][ct][3])
                    : "r"(a[rt][0]), "r"(a[rt][1]), "r"(a[rt][2]), "r"(a[rt][3]),
                      "r"(b[ct][0]), "r"(b[ct][1]));
            }
    }

    // store C as fp16 messages
    #pragma unroll
    for (int rt = 0; rt < 2; rt++) {
        #pragma unroll
        for (int ct = 0; ct < 8; ct++) {
            int r1 = row0 + rw + rt*16 + gid;
            int col = cw + ct*8 + tig*2;
            if (r1 < NN)
                *(__half2*)(g_half + (size_t)r1*DD + col) = __floats2half2_rn(c[rt][ct][0], c[rt][ct][1]);
            int r2 = r1 + 8;
            if (r2 < NN)
                *(__half2*)(g_half + (size_t)r2*DD + col) = __floats2half2_rn(c[rt][ct][2], c[rt][ct][3]);
        }
    }
}

// ---------------- fused CSR gather (one node/warp, 8-wide unroll, fp16 out) ----------------
__device__ __forceinline__ float4 h4tof4(uint2 r) {
    __half2 a = *(__half2*)&r.x;
    __half2 b = *(__half2*)&r.y;
    float2 fa = __half22float2(a), fb = __half22float2(b);
    return make_float4(fa.x, fa.y, fb.x, fb.y);
}

__device__ __forceinline__ void fma4(float4& acc, float w, float4 v) {
    acc.x = fmaf(w, v.x, acc.x);
    acc.y = fmaf(w, v.y, acc.y);
    acc.z = fmaf(w, v.z, acc.z);
    acc.w = fmaf(w, v.w, acc.w);
}

__global__ __launch_bounds__(256) void k_gather(const float* __restrict__ bias,
                                                const int* __restrict__ batch,
                                                int off_l) {
    int n = blockIdx.x*8 + (threadIdx.x >> 5);
    if (n >= NN) return;
    int lane = threadIdx.x & 31;

    int e0 = g_off[n];
    int e1 = g_off[n + 1];
    float di = g_dinv[n];

    uint2 sraw = *(const uint2*)(g_half + (size_t)n*DD + lane*4);
    float4 sv = h4tof4(sraw);
    float w = di * di;
    float4 acc = make_float4(w*sv.x, w*sv.y, w*sv.z, w*sv.w);

    int e = e0;
    for (; e + 8 <= e1; e += 8) {
        float2 m0 = g_meta[e];
        float2 m1 = g_meta[e+1];
        float2 m2 = g_meta[e+2];
        float2 m3 = g_meta[e+3];
        float2 m4 = g_meta[e+4];
        float2 m5 = g_meta[e+5];
        float2 m6 = g_meta[e+6];
        float2 m7 = g_meta[e+7];
        uint2 r0 = *(const uint2*)(g_half + (size_t)__float_as_int(m0.x)*DD + lane*4);
        uint2 r1 = *(const uint2*)(g_half + (size_t)__float_as_int(m1.x)*DD + lane*4);
        uint2 r2 = *(const uint2*)(g_half + (size_t)__float_as_int(m2.x)*DD + lane*4);
        uint2 r3 = *(const uint2*)(g_half + (size_t)__float_as_int(m3.x)*DD + lane*4);
        uint2 r4 = *(const uint2*)(g_half + (size_t)__float_as_int(m4.x)*DD + lane*4);
        uint2 r5 = *(const uint2*)(g_half + (size_t)__float_as_int(m5.x)*DD + lane*4);
        uint2 r6 = *(const uint2*)(g_half + (size_t)__float_as_int(m6.x)*DD + lane*4);
        uint2 r7 = *(const uint2*)(g_half + (size_t)__float_as_int(m7.x)*DD + lane*4);
        fma4(acc, m0.y, h4tof4(r0));
        fma4(acc, m1.y, h4tof4(r1));
        fma4(acc, m2.y, h4tof4(r2));
        fma4(acc, m3.y, h4tof4(r3));
        fma4(acc, m4.y, h4tof4(r4));
        fma4(acc, m5.y, h4tof4(r5));
        fma4(acc, m6.y, h4tof4(r6));
        fma4(acc, m7.y, h4tof4(r7));
    }
    for (; e + 2 <= e1; e += 2) {
        float2 m0 = g_meta[e];
        float2 m1 = g_meta[e+1];
        uint2 r0 = *(const uint2*)(g_half + (size_t)__float_as_int(m0.x)*DD + lane*4);
        uint2 r1 = *(const uint2*)(g_half + (size_t)__float_as_int(m1.x)*DD + lane*4);
        fma4(acc, m0.y, h4tof4(r0));
        fma4(acc, m1.y, h4tof4(r1));
    }
    if (e < e1) {
        float2 m0 = g_meta[e];
        uint2 r0 = *(const uint2*)(g_half + (size_t)__float_as_int(m0.x)*DD + lane*4);
        fma4(acc, m0.y, h4tof4(r0));
    }

    float4 b4 = ((const float4*)bias)[lane];
    acc.x = fmaxf(acc.x + b4.x, 0.f);
    acc.y = fmaxf(acc.y + b4.y, 0.f);
    acc.z = fmaxf(acc.z + b4.z, 0.f);
    acc.w = fmaxf(acc.w + b4.w, 0.f);

    uint2 hv;
    *(__half2*)&hv.x = __floats2half2_rn(acc.x, acc.y);
    *(__half2*)&hv.y = __floats2half2_rn(acc.z, acc.w);
    *(uint2*)(g_jk + (size_t)n*JK + off_l + lane*4) = hv;

    int g = batch[n];
    float* q = g_pooled + g*JK + off_l + lane*4;
    asm volatile("red.global.add.v4.f32 [%0], {%1,%2,%3,%4};"
                 :: "l"(q), "f"(acc.x), "f"(acc.y), "f"(acc.z), "f"(acc.w) : "memory");
}

// ---------------- head ----------------
__global__ __launch_bounds__(128) void k_head1(const float* __restrict__ l1w,
                                               const float* __restrict__ l1b) {
    int g = blockIdx.x;
    int j = threadIdx.x;
    __shared__ float ps[JK];
    float inv = 1.f / fmaxf(g_cnt[g], 1.f);
    for (int k = j; k < JK; k += 128) ps[k] = g_pooled[g*JK + k] * inv;
    __syncthreads();
    float s = l1b[j];
    #pragma unroll 4
    for (int k = 0; k < JK; k++) s = fmaf(ps[k], l1w[k*DD + j], s);
    g_dense[g*DD + j] = fmaxf(s, 0.f);
}

__global__ __launch_bounds__(64) void k_head2(const float* __restrict__ l2w,
                                              const float* __restrict__ l2b,
                                              float* __restrict__ out) {
    __shared__ float ws[DD*10];
    __shared__ float bs[10];
    int t = threadIdx.x;
    for (int i = t; i < DD*10; i += 64) ws[i] = l2w[i];
    if (t < 10) bs[t] = l2b[t];
    __syncthreads();
    if (t < NG) {
        float z[10];
        #pragma unroll
        for (int c = 0; c < 10; c++) z[c] = bs[c];
        for (int k = 0; k < DD; k++) {
            float gv = g_dense[t*DD + k];
            #pragma unroll
            for (int c = 0; c < 10; c++) z[c] = fmaf(gv, ws[k*10 + c], z[c]);
        }
        float m = z[0];
        #pragma unroll
        for (int c = 1; c < 10; c++) m = fmaxf(m, z[c]);
        float ssum = 0.f;
        #pragma unroll
        for (int c = 0; c < 10; c++) ssum += expf(z[c] - m);
        float ls = m + logf(ssum);
        #pragma unroll
        for (int c = 0; c < 10; c++) out[t*10 + c] = z[c] - ls;
    }
}

// ---------------- launch (serial; gemm1 placed 4th for ncu) ----------------
#define GEMM_SMEM (2*128*XSH*2)   // 69632 bytes

extern "C" void kernel_launch(void* const* d_in, const int* in_sizes, int n_in,
                              void* d_out, int out_size) {
    const float* x     = (const float*)d_in[0];
    const int*   ei    = (const int*)  d_in[1];
    const int*   batch = (const int*)  d_in[2];
    const float* W1 = (const float*)d_in[4];  const float* b1 = (const float*)d_in[5];
    const float* W2 = (const float*)d_in[6];  const float* b2 = (const float*)d_in[7];
    const float* W3 = (const float*)d_in[8];  const float* b3 = (const float*)d_in[9];
    const float* l1w = (const float*)d_in[10]; const float* l1b = (const float*)d_in[11];
    const float* l2w = (const float*)d_in[12]; const float* l2b = (const float*)d_in[13];
    float* out = (float*)d_out;

    static int once = 0;
    if (!once) {
        cudaFuncSetAttribute(k_gemm_tc, cudaFuncAttributeMaxDynamicSharedMemorySize, GEMM_SMEM);
        once = 1;
    }

    k_init    <<<(NN + 255)/256, 256>>>();                                   // 1
    k_deg     <<<(NE + 255)/256, 256>>>(ei);                                 // 2
    k_dinv_cnt<<<(NN + 255)/256, 256>>>(batch);                              // 3
    k_gemm_tc <<<(NN + 127)/128, 256, GEMM_SMEM>>>(x, W1, 0);                // 4 (profiled)
    k_scan1   <<<NB_SCAN, 1024>>>();                                         // 5
    k_scan23  <<<(NN + 255)/256, 256>>>();                                   // 6
    k_reorder <<<(NE + 255)/256, 256>>>(ei);                                 // 7

    k_gather  <<<(NN + 7)/8, 256>>>(b1, batch, 0*DD);
    k_gemm_tc <<<(NN + 127)/128, 256, GEMM_SMEM>>>(x, W2, 1);
    k_gather  <<<(NN + 7)/8, 256>>>(b2, batch, 1*DD);
    k_gemm_tc <<<(NN + 127)/128, 256, GEMM_SMEM>>>(x, W3, 2);
    k_gather  <<<(NN + 7)/8, 256>>>(b3, batch, 2*DD);

    k_head1<<<NG, 128>>>(l1w, l1b);
    k_head2<<<1, 64>>>(l2w, l2b, out);
}

// round 14
// speedup vs baseline: 2.2818x; 1.0607x over previous
#include <cuda_runtime.h>
#include <cuda_fp16.h>
#include <math.h>

#define NN 100000
#define NE 1600000
#define DD 128
#define NG 64
#define JK (3*DD)   // 384

#define NB_SCAN 98          // ceil(NN/1024)
#define XSH 136             // smem row stride in halves (272B -> LDSM conflict-free, 16B-aligned)

// ---------------- scratch (device globals) ----------------
__device__ float  g_dinv[NN];
__device__ int    g_deg[NN];
__device__ int    g_inc[NN];
__device__ int    g_part[NB_SCAN];
__device__ int    g_off[NN + 1];
__device__ int    g_fill[NN];
__device__ float2 g_meta[NE];                 // {src byte-offset bits, norm}, dst-sorted
__device__ __half g_xh[(size_t)NN*DD];        // fp16 copy of input X
__device__ __half g_wh[3*DD*DD];              // fp16 W1|W2|W3, [k][n] row-major
__device__ __half g_half[(size_t)NN*DD];      // GEMM output messages (fp16)
__device__ __half g_jk[(size_t)NN*JK];        // JK-concat layer outputs (fp16)
__device__ float  g_pooled[NG*JK];
__device__ float  g_cnt[NG];
__device__ float  g_dense[NG*DD];

// ---------------- converts ----------------
__global__ void k_x2h(const float* __restrict__ x) {
    int i = blockIdx.x*256 + threadIdx.x;     // NN*DD/4 = 3.2M float4
    if (i < NN*DD/4) {
        float4 v = ((const float4*)x)[i];
        uint2 hv;
        *(__half2*)&hv.x = __floats2half2_rn(v.x, v.y);
        *(__half2*)&hv.y = __floats2half2_rn(v.z, v.w);
        ((uint2*)g_xh)[i] = hv;
    }
}

__global__ void k_wcvt(const float* __restrict__ W1,
                       const float* __restrict__ W2,
                       const float* __restrict__ W3) {
    int i = blockIdx.x*256 + threadIdx.x;     // 3*4096 float4
    int l = i >> 12, j = i & 4095;
    if (l < 3) {
        const float* W = (l == 0) ? W1 : (l == 1) ? W2 : W3;
        float4 v = ((const float4*)W)[j];
        uint2 hv;
        *(__half2*)&hv.x = __floats2half2_rn(v.x, v.y);
        *(__half2*)&hv.y = __floats2half2_rn(v.z, v.w);
        ((uint2*)(g_wh + l*DD*DD))[j] = hv;
    }
}

// ---------------- preprocessing ----------------
__global__ void k_init() {
    int i = blockIdx.x*256 + threadIdx.x;
    if (i < NN) g_deg[i] = 0;
    if (i < NG*JK) g_pooled[i] = 0.0f;
    if (i < NG) g_cnt[i] = 0.0f;
}

__global__ void k_deg(const int* __restrict__ ei) {
    int e = blockIdx.x*256 + threadIdx.x;
    if (e < NE) atomicAdd(&g_deg[ei[NE + e]], 1);
}

__global__ void k_dinv_cnt(const int* __restrict__ batch) {
    int i = blockIdx.x*256 + threadIdx.x;
    if (i < NN) {
        g_dinv[i] = rsqrtf((float)g_deg[i] + 1.0f);
        atomicAdd(&g_cnt[batch[i]], 1.0f);
    }
}

__global__ __launch_bounds__(1024) void k_scan1() {
    __shared__ int sh[1024];
    int t = threadIdx.x;
    int i = blockIdx.x*1024 + t;
    int v = (i < NN) ? g_deg[i] : 0;
    sh[t] = v;
    __syncthreads();
    for (int off = 1; off < 1024; off <<= 1) {
        int add = (t >= off) ? sh[t - off] : 0;
        __syncthreads();
        sh[t] += add;
        __syncthreads();
    }
    if (i < NN) g_inc[i] = sh[t];
    if (t == 1023) g_part[blockIdx.x] = sh[1023];
}

__global__ __launch_bounds__(256) void k_scan23() {
    __shared__ int sp[NB_SCAN];
    __shared__ int pref;
    int t = threadIdx.x;
    if (t < NB_SCAN) sp[t] = g_part[t];
    __syncthreads();
    int b = blockIdx.x >> 2;
    if (t == 0) {
        int run = 0;
        for (int q = 0; q < b; q++) run += sp[q];
        pref = run;
    }
    __syncthreads();
    int i = blockIdx.x*256 + t;
    if (i < NN) {
        int off = g_inc[i] - g_deg[i] + pref;
        g_off[i] = off;
        g_fill[i] = off;
    }
    if (i == 0) g_off[NN] = NE;
}

__global__ void k_reorder(const int* __restrict__ ei) {
    int e = blockIdx.x*256 + threadIdx.x;
    if (e < NE) {
        int s = ei[e];
        int d = ei[NE + e];
        int pos = atomicAdd(&g_fill[d], 1);
        float2 m;
        m.x = __int_as_float(s * (DD*2));     // byte offset of source row
        m.y = g_dinv[s] * g_dinv[d];
        g_meta[pos] = m;
    }
}

// ---------------- fp16 GEMM: cp.async staging + LDSM + HMMA ----------------
__device__ __forceinline__ void cp16(unsigned saddr, const void* gptr) {
    asm volatile("cp.async.cg.shared.global [%0], [%1], 16;" :: "r"(saddr), "l"(gptr));
}

__global__ __launch_bounds__(256, 3) void k_gemm_tc(const __half* __restrict__ Xsrc,
                                                    int xstride,
                                                    const __half* __restrict__ Wsrc) {
    extern __shared__ __half sh[];
    __half* Xs = sh;                    // X tile [r][k], 128 x XSH halves
    __half* Ws = sh + 128*XSH;          // W [k][n] row-major, 128 x XSH halves

    int t = threadIdx.x;
    int row0 = blockIdx.x * 128;

    unsigned XsA = (unsigned)__cvta_generic_to_shared(Xs);
    unsigned WsA = (unsigned)__cvta_generic_to_shared(Ws);

    // stage W tile: 128 rows x 16 chunks(16B)
    #pragma unroll
    for (int j = 0; j < 8; j++) {
        int idx = t + j*256;
        int r = idx >> 4, ch = idx & 15;
        cp16(WsA + (unsigned)((r*XSH + ch*8) * 2), Wsrc + r*DD + ch*8);
    }
    // stage X tile
    #pragma unroll
    for (int j = 0; j < 8; j++) {
        int idx = t + j*256;
        int r = idx >> 4, ch = idx & 15;
        int row = row0 + r;
        unsigned sa = XsA + (unsigned)((r*XSH + ch*8) * 2);
        if (row < NN) {
            cp16(sa, Xsrc + (size_t)row*xstride + ch*8);
        } else {
            uint4 z = make_uint4(0,0,0,0);
            asm volatile("st.shared.v4.b32 [%0], {%1,%2,%3,%4};"
                         :: "r"(sa), "r"(z.x), "r"(z.y), "r"(z.z), "r"(z.w));
        }
    }
    asm volatile("cp.async.commit_group;");
    asm volatile("cp.async.wait_group 0;");
    __syncthreads();

    int w = t >> 5, lane = t & 31;
    int gid = lane >> 2, tig = lane & 3;
    int rw = (w & 3) * 32;
    int cw = (w >> 2) * 64;
    int l15 = lane & 15;
    int lhi = (lane >> 4) * 8;

    unsigned aAddr0 = XsA + (unsigned)(((rw + l15)*XSH + lhi) * 2);
    unsigned bAddr0 = WsA + (unsigned)((l15*XSH + cw + lhi) * 2);

    float c[2][8][4];
    #pragma unroll
    for (int rt = 0; rt < 2; rt++)
        #pragma unroll
        for (int ct = 0; ct < 8; ct++)
            c[rt][ct][0] = c[rt][ct][1] = c[rt][ct][2] = c[rt][ct][3] = 0.f;

    #pragma unroll
    for (int ks = 0; ks < 8; ks++) {
        unsigned a[2][4], b[8][2];
        #pragma unroll
        for (int rt = 0; rt < 2; rt++) {
            unsigned ad = aAddr0 + rt*(16*XSH*2) + ks*32;
            asm volatile("ldmatrix.sync.aligned.m8n8.x4.shared.b16 {%0,%1,%2,%3}, [%4];"
                         : "=r"(a[rt][0]), "=r"(a[rt][1]), "=r"(a[rt][2]), "=r"(a[rt][3])
                         : "r"(ad));
        }
        #pragma unroll
        for (int pr = 0; pr < 4; pr++) {
            unsigned bd = bAddr0 + ks*(16*XSH*2) + pr*32;
            asm volatile("ldmatrix.sync.aligned.m8n8.x4.trans.shared.b16 {%0,%1,%2,%3}, [%4];"
                         : "=r"(b[2*pr][0]), "=r"(b[2*pr][1]), "=r"(b[2*pr+1][0]), "=r"(b[2*pr+1][1])
                         : "r"(bd));
        }
        #pragma unroll
        for (int rt = 0; rt < 2; rt++)
            #pragma unroll
            for (int ct = 0; ct < 8; ct++) {
                asm volatile(
                    "mma.sync.aligned.m16n8k16.row.col.f32.f16.f16.f32 "
                    "{%0,%1,%2,%3}, {%4,%5,%6,%7}, {%8,%9}, {%0,%1,%2,%3};"
                    : "+f"(c[rt][ct][0]), "+f"(c[rt][ct][1]),
                      "+f"(c[rt][ct][2]), "+f"(c[rt][ct][3])
                    : "r"(a[rt][0]), "r"(a[rt][1]), "r"(a[rt][2]), "r"(a[rt][3]),
                      "r"(b[ct][0]), "r"(b[ct][1]));
            }
    }

    #pragma unroll
    for (int rt = 0; rt < 2; rt++) {
        #pragma unroll
        for (int ct = 0; ct < 8; ct++) {
            int r1 = row0 + rw + rt*16 + gid;
            int col = cw + ct*8 + tig*2;
            if (r1 < NN)
                *(__half2*)(g_half + (size_t)r1*DD + col) = __floats2half2_rn(c[rt][ct][0], c[rt][ct][1]);
            int r2 = r1 + 8;
            if (r2 < NN)
                *(__half2*)(g_half + (size_t)r2*DD + col) = __floats2half2_rn(c[rt][ct][2], c[rt][ct][3]);
        }
    }
}

// ---------------- fused CSR gather (one node/warp, 8-wide unroll) ----------------
__device__ __forceinline__ float4 h4tof4(uint2 r) {
    __half2 a = *(__half2*)&r.x;
    __half2 b = *(__half2*)&r.y;
    float2 fa = __half22float2(a), fb = __half22float2(b);
    return make_float4(fa.x, fa.y, fb.x, fb.y);
}

__device__ __forceinline__ void fma4(float4& acc, float w, float4 v) {
    acc.x = fmaf(w, v.x, acc.x);
    acc.y = fmaf(w, v.y, acc.y);
    acc.z = fmaf(w, v.z, acc.z);
    acc.w = fmaf(w, v.w, acc.w);
}

__global__ __launch_bounds__(256) void k_gather(const float* __restrict__ bias,
                                                const int* __restrict__ batch,
                                                int off_l) {
    int n = blockIdx.x*8 + (threadIdx.x >> 5);
    if (n >= NN) return;
    int lane = threadIdx.x & 31;

    int e0 = g_off[n];
    int e1 = g_off[n + 1];
    float di = g_dinv[n];

    const char* hbase = (const char*)g_half + lane*8;   // lane's 8B slice

    uint2 sraw = *(const uint2*)(hbase + (size_t)n*(DD*2));
    float4 sv = h4tof4(sraw);
    float w = di * di;
    float4 acc = make_float4(w*sv.x, w*sv.y, w*sv.z, w*sv.w);

    int e = e0;
    for (; e + 8 <= e1; e += 8) {
        float2 m0 = g_meta[e];
        float2 m1 = g_meta[e+1];
        float2 m2 = g_meta[e+2];
        float2 m3 = g_meta[e+3];
        float2 m4 = g_meta[e+4];
        float2 m5 = g_meta[e+5];
        float2 m6 = g_meta[e+6];
        float2 m7 = g_meta[e+7];
        uint2 r0 = *(const uint2*)(hbase + (unsigned)__float_as_int(m0.x));
        uint2 r1 = *(const uint2*)(hbase + (unsigned)__float_as_int(m1.x));
        uint2 r2 = *(const uint2*)(hbase + (unsigned)__float_as_int(m2.x));
        uint2 r3 = *(const uint2*)(hbase + (unsigned)__float_as_int(m3.x));
        uint2 r4 = *(const uint2*)(hbase + (unsigned)__float_as_int(m4.x));
        uint2 r5 = *(const uint2*)(hbase + (unsigned)__float_as_int(m5.x));
        uint2 r6 = *(const uint2*)(hbase + (unsigned)__float_as_int(m6.x));
        uint2 r7 = *(const uint2*)(hbase + (unsigned)__float_as_int(m7.x));
        fma4(acc, m0.y, h4tof4(r0));
        fma4(acc, m1.y, h4tof4(r1));
        fma4(acc, m2.y, h4tof4(r2));
        fma4(acc, m3.y, h4tof4(r3));
        fma4(acc, m4.y, h4tof4(r4));
        fma4(acc, m5.y, h4tof4(r5));
        fma4(acc, m6.y, h4tof4(r6));
        fma4(acc, m7.y, h4tof4(r7));
    }
    for (; e + 2 <= e1; e += 2) {
        float2 m0 = g_meta[e];
        float2 m1 = g_meta[e+1];
        uint2 r0 = *(const uint2*)(hbase + (unsigned)__float_as_int(m0.x));
        uint2 r1 = *(const uint2*)(hbase + (unsigned)__float_as_int(m1.x));
        fma4(acc, m0.y, h4tof4(r0));
        fma4(acc, m1.y, h4tof4(r1));
    }
    if (e < e1) {
        float2 m0 = g_meta[e];
        uint2 r0 = *(const uint2*)(hbase + (unsigned)__float_as_int(m0.x));
        fma4(acc, m0.y, h4tof4(r0));
    }

    float4 b4 = ((const float4*)bias)[lane];
    acc.x = fmaxf(acc.x + b4.x, 0.f);
    acc.y = fmaxf(acc.y + b4.y, 0.f);
    acc.z = fmaxf(acc.z + b4.z, 0.f);
    acc.w = fmaxf(acc.w + b4.w, 0.f);

    uint2 hv;
    *(__half2*)&hv.x = __floats2half2_rn(acc.x, acc.y);
    *(__half2*)&hv.y = __floats2half2_rn(acc.z, acc.w);
    *(uint2*)(g_jk + (size_t)n*JK + off_l + lane*4) = hv;

    int g = batch[n];
    float* q = g_pooled + g*JK + off_l + lane*4;
    asm volatile("red.global.add.v4.f32 [%0], {%1,%2,%3,%4};"
                 :: "l"(q), "f"(acc.x), "f"(acc.y), "f"(acc.z), "f"(acc.w) : "memory");
}

// ---------------- head ----------------
__global__ __launch_bounds__(128) void k_head1(const float* __restrict__ l1w,
                                               const float* __restrict__ l1b) {
    int g = blockIdx.x;
    int j = threadIdx.x;
    __shared__ float ps[JK];
    float inv = 1.f / fmaxf(g_cnt[g], 1.f);
    for (int k = j; k < JK; k += 128) ps[k] = g_pooled[g*JK + k] * inv;
    __syncthreads();
    float s = l1b[j];
    #pragma unroll 4
    for (int k = 0; k < JK; k++) s = fmaf(ps[k], l1w[k*DD + j], s);
    g_dense[g*DD + j] = fmaxf(s, 0.f);
}

__global__ __launch_bounds__(64) void k_head2(const float* __restrict__ l2w,
                                              const float* __restrict__ l2b,
                                              float* __restrict__ out) {
    __shared__ float ws[DD*10];
    __shared__ float bs[10];
    int t = threadIdx.x;
    for (int i = t; i < DD*10; i += 64) ws[i] = l2w[i];
    if (t < 10) bs[t] = l2b[t];
    __syncthreads();
    if (t < NG) {
        float z[10];
        #pragma unroll
        for (int c = 0; c < 10; c++) z[c] = bs[c];
        for (int k = 0; k < DD; k++) {
            float gv = g_dense[t*DD + k];
            #pragma unroll
            for (int c = 0; c < 10; c++) z[c] = fmaf(gv, ws[k*10 + c], z[c]);
        }
        float m = z[0];
        #pragma unroll
        for (int c = 1; c < 10; c++) m = fmaxf(m, z[c]);
        float ssum = 0.f;
        #pragma unroll
        for (int c = 0; c < 10; c++) ssum += expf(z[c] - m);
        float ls = m + logf(ssum);
        #pragma unroll
        for (int c = 0; c < 10; c++) out[t*10 + c] = z[c] - ls;
    }
}

// ---------------- launch (serial; gemm1 placed 4th for ncu) ----------------
#define GEMM_SMEM (2*128*XSH*2)   // 69632 bytes

extern "C" void kernel_launch(void* const* d_in, const int* in_sizes, int n_in,
                              void* d_out, int out_size) {
    const float* x     = (const float*)d_in[0];
    const int*   ei    = (const int*)  d_in[1];
    const int*   batch = (const int*)  d_in[2];
    const float* W1 = (const float*)d_in[4];  const float* b1 = (const float*)d_in[5];
    const float* W2 = (const float*)d_in[6];  const float* b2 = (const float*)d_in[7];
    const float* W3 = (const float*)d_in[8];  const float* b3 = (const float*)d_in[9];
    const float* l1w = (const float*)d_in[10]; const float* l1b = (const float*)d_in[11];
    const float* l2w = (const float*)d_in[12]; const float* l2b = (const float*)d_in[13];
    float* out = (float*)d_out;

    static int once = 0;
    if (!once) {
        cudaFuncSetAttribute(k_gemm_tc, cudaFuncAttributeMaxDynamicSharedMemorySize, GEMM_SMEM);
        once = 1;
    }

    // device pointers to __device__ globals (needed as kernel args)
    static __half* d_xh = nullptr;
    static __half* d_wh = nullptr;
    static __half* d_jk = nullptr;
    if (!d_xh) {
        cudaGetSymbolAddress((void**)&d_xh, g_xh);
        cudaGetSymbolAddress((void**)&d_wh, g_wh);
        cudaGetSymbolAddress((void**)&d_jk, g_jk);
    }

    k_x2h     <<<(NN*DD/4 + 255)/256, 256>>>(x);                             // 1
    k_wcvt    <<<(3*4096 + 255)/256, 256>>>(W1, W2, W3);                     // 2
    k_init    <<<(NN + 255)/256, 256>>>();                                   // 3
    k_gemm_tc <<<(NN + 127)/128, 256, GEMM_SMEM>>>(d_xh, DD, d_wh);          // 4 (profiled)
    k_deg     <<<(NE + 255)/256, 256>>>(ei);                                 // 5
    k_dinv_cnt<<<(NN + 255)/256, 256>>>(batch);                              // 6
    k_scan1   <<<NB_SCAN, 1024>>>();                                         // 7
    k_scan23  <<<(NN + 255)/256, 256>>>();                                   // 8
    k_reorder <<<(NE + 255)/256, 256>>>(ei);                                 // 9

    k_gather  <<<(NN + 7)/8, 256>>>(b1, batch, 0*DD);
    k_gemm_tc <<<(NN + 127)/128, 256, GEMM_SMEM>>>(d_jk + 0*DD, JK, d_wh + 1*DD*DD);
    k_gather  <<<(NN + 7)/8, 256>>>(b2, batch, 1*DD);
    k_gemm_tc <<<(NN + 127)/128, 256, GEMM_SMEM>>>(d_jk + 1*DD, JK, d_wh + 2*DD*DD);
    k_gather  <<<(NN + 7)/8, 256>>>(b3, batch, 2*DD);

    k_head1<<<NG, 128>>>(l1w, l1b);
    k_head2<<<1, 64>>>(l2w, l2b, out);
}

// round 15
// speedup vs baseline: 2.9248x; 1.2818x over previous
#include <cuda_runtime.h>
#include <cuda_fp16.h>
#include <math.h>

#define NN 100000
#define NE 1600000
#define DD 128
#define NG 64
#define JK (3*DD)   // 384

#define NB_SCAN 98          // ceil(NN/1024)
#define XSH 136             // smem row stride in halves (272B -> LDSM conflict-free, 16B-aligned)

// ---------------- scratch (device globals) ----------------
__device__ float  g_dinv[NN];
__device__ int    g_deg[NN];
__device__ int    g_inc[NN];
__device__ int    g_part[NB_SCAN];
__device__ int    g_off[NN + 1];
__device__ int    g_fill[NN];
__device__ float2 g_meta[NE];                 // {src byte-offset bits, norm}, dst-sorted
__device__ __half g_xh[(size_t)NN*DD];        // fp16 copy of input X
__device__ __half g_wh[3*DD*DD];              // fp16 W1|W2|W3, [k][n] row-major
__device__ __half g_half[(size_t)NN*DD];      // GEMM output messages (fp16)
__device__ __half g_jk[(size_t)NN*JK];        // JK-concat layer outputs (fp16)
__device__ float  g_pooled[NG*JK];
__device__ float  g_cnt[NG];
__device__ float  g_dense[NG*DD];

// ---------------- converts ----------------
__global__ void k_x2h(const float* __restrict__ x) {
    int i = blockIdx.x*256 + threadIdx.x;
    if (i < NN*DD/4) {
        float4 v = ((const float4*)x)[i];
        uint2 hv;
        *(__half2*)&hv.x = __floats2half2_rn(v.x, v.y);
        *(__half2*)&hv.y = __floats2half2_rn(v.z, v.w);
        ((uint2*)g_xh)[i] = hv;
    }
}

__global__ void k_wcvt(const float* __restrict__ W1,
                       const float* __restrict__ W2,
                       const float* __restrict__ W3) {
    int i = blockIdx.x*256 + threadIdx.x;
    int l = i >> 12, j = i & 4095;
    if (l < 3) {
        const float* W = (l == 0) ? W1 : (l == 1) ? W2 : W3;
        float4 v = ((const float4*)W)[j];
        uint2 hv;
        *(__half2*)&hv.x = __floats2half2_rn(v.x, v.y);
        *(__half2*)&hv.y = __floats2half2_rn(v.z, v.w);
        ((uint2*)(g_wh + l*DD*DD))[j] = hv;
    }
}

// ---------------- preprocessing ----------------
__global__ void k_init() {
    int i = blockIdx.x*256 + threadIdx.x;
    if (i < NN) g_deg[i] = 0;
    if (i < NG*JK) g_pooled[i] = 0.0f;
    if (i < NG) g_cnt[i] = 0.0f;
}

__global__ void k_deg(const int* __restrict__ ei) {
    int e = blockIdx.x*256 + threadIdx.x;
    if (e < NE) atomicAdd(&g_deg[ei[NE + e]], 1);
}

// dinv + block-aggregated graph node counts (batch is sorted)
__global__ void k_dinv_cnt(const int* __restrict__ batch) {
    int i = blockIdx.x*256 + threadIdx.x;
    if (i < NN) {
        g_dinv[i] = rsqrtf((float)g_deg[i] + 1.0f);
        int g = batch[i];
        bool start = (threadIdx.x == 0) || (batch[i-1] != g);
        if (start) {
            int end = blockIdx.x*256 + 256;
            if (end > NN) end = NN;
            int c = 0;
            for (int j = i; j < end && batch[j] == g; j++) c++;
            atomicAdd(&g_cnt[g], (float)c);
        }
    }
}

__global__ __launch_bounds__(1024) void k_scan1() {
    __shared__ int sh[1024];
    int t = threadIdx.x;
    int i = blockIdx.x*1024 + t;
    int v = (i < NN) ? g_deg[i] : 0;
    sh[t] = v;
    __syncthreads();
    for (int off = 1; off < 1024; off <<= 1) {
        int add = (t >= off) ? sh[t - off] : 0;
        __syncthreads();
        sh[t] += add;
        __syncthreads();
    }
    if (i < NN) g_inc[i] = sh[t];
    if (t == 1023) g_part[blockIdx.x] = sh[1023];
}

__global__ __launch_bounds__(256) void k_scan23() {
    __shared__ int sp[NB_SCAN];
    __shared__ int pref;
    int t = threadIdx.x;
    if (t < NB_SCAN) sp[t] = g_part[t];
    __syncthreads();
    int b = blockIdx.x >> 2;
    if (t == 0) {
        int run = 0;
        for (int q = 0; q < b; q++) run += sp[q];
        pref = run;
    }
    __syncthreads();
    int i = blockIdx.x*256 + t;
    if (i < NN) {
        int off = g_inc[i] - g_deg[i] + pref;
        g_off[i] = off;
        g_fill[i] = off;
    }
    if (i == 0) g_off[NN] = NE;
}

__global__ void k_reorder(const int* __restrict__ ei) {
    int e = blockIdx.x*256 + threadIdx.x;
    if (e < NE) {
        int s = ei[e];
        int d = ei[NE + e];
        int pos = atomicAdd(&g_fill[d], 1);
        float2 m;
        m.x = __int_as_float(s * (DD*2));     // byte offset of source row
        m.y = g_dinv[s] * g_dinv[d];
        g_meta[pos] = m;
    }
}

// ---------------- fp16 GEMM: cp.async staging + LDSM + HMMA ----------------
__device__ __forceinline__ void cp16(unsigned saddr, const void* gptr) {
    asm volatile("cp.async.cg.shared.global [%0], [%1], 16;" :: "r"(saddr), "l"(gptr));
}

__global__ __launch_bounds__(256, 3) void k_gemm_tc(const __half* __restrict__ Xsrc,
                                                    int xstride,
                                                    const __half* __restrict__ Wsrc) {
    extern __shared__ __half sh[];
    __half* Xs = sh;
    __half* Ws = sh + 128*XSH;

    int t = threadIdx.x;
    int row0 = blockIdx.x * 128;

    unsigned XsA = (unsigned)__cvta_generic_to_shared(Xs);
    unsigned WsA = (unsigned)__cvta_generic_to_shared(Ws);

    #pragma unroll
    for (int j = 0; j < 8; j++) {
        int idx = t + j*256;
        int r = idx >> 4, ch = idx & 15;
        cp16(WsA + (unsigned)((r*XSH + ch*8) * 2), Wsrc + r*DD + ch*8);
    }
    #pragma unroll
    for (int j = 0; j < 8; j++) {
        int idx = t + j*256;
        int r = idx >> 4, ch = idx & 15;
        int row = row0 + r;
        unsigned sa = XsA + (unsigned)((r*XSH + ch*8) * 2);
        if (row < NN) {
            cp16(sa, Xsrc + (size_t)row*xstride + ch*8);
        } else {
            uint4 z = make_uint4(0,0,0,0);
            asm volatile("st.shared.v4.b32 [%0], {%1,%2,%3,%4};"
                         :: "r"(sa), "r"(z.x), "r"(z.y), "r"(z.z), "r"(z.w));
        }
    }
    asm volatile("cp.async.commit_group;");
    asm volatile("cp.async.wait_group 0;");
    __syncthreads();

    int w = t >> 5, lane = t & 31;
    int gid = lane >> 2, tig = lane & 3;
    int rw = (w & 3) * 32;
    int cw = (w >> 2) * 64;
    int l15 = lane & 15;
    int lhi = (lane >> 4) * 8;

    unsigned aAddr0 = XsA + (unsigned)(((rw + l15)*XSH + lhi) * 2);
    unsigned bAddr0 = WsA + (unsigned)((l15*XSH + cw + lhi) * 2);

    float c[2][8][4];
    #pragma unroll
    for (int rt = 0; rt < 2; rt++)
        #pragma unroll
        for (int ct = 0; ct < 8; ct++)
            c[rt][ct][0] = c[rt][ct][1] = c[rt][ct][2] = c[rt][ct][3] = 0.f;

    #pragma unroll
    for (int ks = 0; ks < 8; ks++) {
        unsigned a[2][4], b[8][2];
        #pragma unroll
        for (int rt = 0; rt < 2; rt++) {
            unsigned ad = aAddr0 + rt*(16*XSH*2) + ks*32;
            asm volatile("ldmatrix.sync.aligned.m8n8.x4.shared.b16 {%0,%1,%2,%3}, [%4];"
                         : "=r"(a[rt][0]), "=r"(a[rt][1]), "=r"(a[rt][2]), "=r"(a[rt][3])
                         : "r"(ad));
        }
        #pragma unroll
        for (int pr = 0; pr < 4; pr++) {
            unsigned bd = bAddr0 + ks*(16*XSH*2) + pr*32;
            asm volatile("ldmatrix.sync.aligned.m8n8.x4.trans.shared.b16 {%0,%1,%2,%3}, [%4];"
                         : "=r"(b[2*pr][0]), "=r"(b[2*pr][1]), "=r"(b[2*pr+1][0]), "=r"(b[2*pr+1][1])
                         : "r"(bd));
        }
        #pragma unroll
        for (int rt = 0; rt < 2; rt++)
            #pragma unroll
            for (int ct = 0; ct < 8; ct++) {
                asm volatile(
                    "mma.sync.aligned.m16n8k16.row.col.f32.f16.f16.f32 "
                    "{%0,%1,%2,%3}, {%4,%5,%6,%7}, {%8,%9}, {%0,%1,%2,%3};"
                    : "+f"(c[rt][ct][0]), "+f"(c[rt][ct][1]),
                      "+f"(c[rt][ct][2]), "+f"(c[rt][ct][3])
                    : "r"(a[rt][0]), "r"(a[rt][1]), "r"(a[rt][2]), "r"(a[rt][3]),
                      "r"(b[ct][0]), "r"(b[ct][1]));
            }
    }

    #pragma unroll
    for (int rt = 0; rt < 2; rt++) {
        #pragma unroll
        for (int ct = 0; ct < 8; ct++) {
            int r1 = row0 + rw + rt*16 + gid;
            int col = cw + ct*8 + tig*2;
            if (r1 < NN)
                *(__half2*)(g_half + (size_t)r1*DD + col) = __floats2half2_rn(c[rt][ct][0], c[rt][ct][1]);
            int r2 = r1 + 8;
            if (r2 < NN)
                *(__half2*)(g_half + (size_t)r2*DD + col) = __floats2half2_rn(c[rt][ct][2], c[rt][ct][3]);
        }
    }
}

// ---------------- fused CSR gather + block-aggregated pooling ----------------
__device__ __forceinline__ float4 h4tof4(uint2 r) {
    __half2 a = *(__half2*)&r.x;
    __half2 b = *(__half2*)&r.y;
    float2 fa = __half22float2(a), fb = __half22float2(b);
    return make_float4(fa.x, fa.y, fb.x, fb.y);
}

__device__ __forceinline__ void fma4(float4& acc, float w, float4 v) {
    acc.x = fmaf(w, v.x, acc.x);
    acc.y = fmaf(w, v.y, acc.y);
    acc.z = fmaf(w, v.z, acc.z);
    acc.w = fmaf(w, v.w, acc.w);
}

// block = 512 threads = 16 warps = 16 nodes (NN = 6250*16 exactly)
__global__ __launch_bounds__(512, 2) void k_gather(const float* __restrict__ bias,
                                                   const int* __restrict__ batch,
                                                   int off_l) {
    __shared__ float sacc[16*128];
    __shared__ int   sg[16];

    int t = threadIdx.x;
    int wid = t >> 5;
    int lane = t & 31;
    int n = blockIdx.x*16 + wid;

    int e0 = g_off[n];
    int e1 = g_off[n + 1];
    float di = g_dinv[n];

    const char* hbase = (const char*)g_half + lane*8;

    uint2 sraw = *(const uint2*)(hbase + (size_t)n*(DD*2));
    float4 sv = h4tof4(sraw);
    float w = di * di;
    float4 acc = make_float4(w*sv.x, w*sv.y, w*sv.z, w*sv.w);

    int e = e0;
    for (; e + 8 <= e1; e += 8) {
        float2 m0 = g_meta[e];
        float2 m1 = g_meta[e+1];
        float2 m2 = g_meta[e+2];
        float2 m3 = g_meta[e+3];
        float2 m4 = g_meta[e+4];
        float2 m5 = g_meta[e+5];
        float2 m6 = g_meta[e+6];
        float2 m7 = g_meta[e+7];
        uint2 r0 = *(const uint2*)(hbase + (unsigned)__float_as_int(m0.x));
        uint2 r1 = *(const uint2*)(hbase + (unsigned)__float_as_int(m1.x));
        uint2 r2 = *(const uint2*)(hbase + (unsigned)__float_as_int(m2.x));
        uint2 r3 = *(const uint2*)(hbase + (unsigned)__float_as_int(m3.x));
        uint2 r4 = *(const uint2*)(hbase + (unsigned)__float_as_int(m4.x));
        uint2 r5 = *(const uint2*)(hbase + (unsigned)__float_as_int(m5.x));
        uint2 r6 = *(const uint2*)(hbase + (unsigned)__float_as_int(m6.x));
        uint2 r7 = *(const uint2*)(hbase + (unsigned)__float_as_int(m7.x));
        fma4(acc, m0.y, h4tof4(r0));
        fma4(acc, m1.y, h4tof4(r1));
        fma4(acc, m2.y, h4tof4(r2));
        fma4(acc, m3.y, h4tof4(r3));
        fma4(acc, m4.y, h4tof4(r4));
        fma4(acc, m5.y, h4tof4(r5));
        fma4(acc, m6.y, h4tof4(r6));
        fma4(acc, m7.y, h4tof4(r7));
    }
    for (; e + 2 <= e1; e += 2) {
        float2 m0 = g_meta[e];
        float2 m1 = g_meta[e+1];
        uint2 r0 = *(const uint2*)(hbase + (unsigned)__float_as_int(m0.x));
        uint2 r1 = *(const uint2*)(hbase + (unsigned)__float_as_int(m1.x));
        fma4(acc, m0.y, h4tof4(r0));
        fma4(acc, m1.y, h4tof4(r1));
    }
    if (e < e1) {
        float2 m0 = g_meta[e];
        uint2 r0 = *(const uint2*)(hbase + (unsigned)__float_as_int(m0.x));
        fma4(acc, m0.y, h4tof4(r0));
    }

    float4 b4 = ((const float4*)bias)[lane];
    acc.x = fmaxf(acc.x + b4.x, 0.f);
    acc.y = fmaxf(acc.y + b4.y, 0.f);
    acc.z = fmaxf(acc.z + b4.z, 0.f);
    acc.w = fmaxf(acc.w + b4.w, 0.f);

    uint2 hv;
    *(__half2*)&hv.x = __floats2half2_rn(acc.x, acc.y);
    *(__half2*)&hv.y = __floats2half2_rn(acc.z, acc.w);
    *(uint2*)(g_jk + (size_t)n*JK + off_l + lane*4) = hv;

    // stage for block pooling
    *(float4*)(sacc + wid*128 + lane*4) = acc;
    if (lane == 0) sg[wid] = batch[n];
    __syncthreads();

    // segmented reduction over the 16 nodes (batch sorted -> contiguous runs)
    if (t < 32) {
        float4 run = *(float4*)(sacc + t*4);
        int cur = sg[0];
        #pragma unroll
        for (int r = 1; r < 16; r++) {
            int g = sg[r];
            float4 v = *(float4*)(sacc + r*128 + t*4);
            if (g != cur) {
                float* q = g_pooled + cur*JK + off_l + t*4;
                asm volatile("red.global.add.v4.f32 [%0], {%1,%2,%3,%4};"
                             :: "l"(q), "f"(run.x), "f"(run.y), "f"(run.z), "f"(run.w) : "memory");
                run = v; cur = g;
            } else {
                run.x += v.x; run.y += v.y; run.z += v.z; run.w += v.w;
            }
        }
        float* q = g_pooled + cur*JK + off_l + t*4;
        asm volatile("red.global.add.v4.f32 [%0], {%1,%2,%3,%4};"
                     :: "l"(q), "f"(run.x), "f"(run.y), "f"(run.z), "f"(run.w) : "memory");
    }
}

// ---------------- head ----------------
__global__ __launch_bounds__(128) void k_head1(const float* __restrict__ l1w,
                                               const float* __restrict__ l1b) {
    int g = blockIdx.x;
    int j = threadIdx.x;
    __shared__ float ps[JK];
    float inv = 1.f / fmaxf(g_cnt[g], 1.f);
    for (int k = j; k < JK; k += 128) ps[k] = g_pooled[g*JK + k] * inv;
    __syncthreads();
    float s = l1b[j];
    #pragma unroll 4
    for (int k = 0; k < JK; k++) s = fmaf(ps[k], l1w[k*DD + j], s);
    g_dense[g*DD + j] = fmaxf(s, 0.f);
}

__global__ __launch_bounds__(64) void k_head2(const float* __restrict__ l2w,
                                              const float* __restrict__ l2b,
                                              float* __restrict__ out) {
    __shared__ float ws[DD*10];
    __shared__ float bs[10];
    int t = threadIdx.x;
    for (int i = t; i < DD*10; i += 64) ws[i] = l2w[i];
    if (t < 10) bs[t] = l2b[t];
    __syncthreads();
    if (t < NG) {
        float z[10];
        #pragma unroll
        for (int c = 0; c < 10; c++) z[c] = bs[c];
        for (int k = 0; k < DD; k++) {
            float gv = g_dense[t*DD + k];
            #pragma unroll
            for (int c = 0; c < 10; c++) z[c] = fmaf(gv, ws[k*10 + c], z[c]);
        }
        float m = z[0];
        #pragma unroll
        for (int c = 1; c < 10; c++) m = fmaxf(m, z[c]);
        float ssum = 0.f;
        #pragma unroll
        for (int c = 0; c < 10; c++) ssum += expf(z[c] - m);
        float ls = m + logf(ssum);
        #pragma unroll
        for (int c = 0; c < 10; c++) out[t*10 + c] = z[c] - ls;
    }
}

// ---------------- launch (serial; gemm1 placed 4th for ncu) ----------------
#define GEMM_SMEM (2*128*XSH*2)   // 69632 bytes

extern "C" void kernel_launch(void* const* d_in, const int* in_sizes, int n_in,
                              void* d_out, int out_size) {
    const float* x     = (const float*)d_in[0];
    const int*   ei    = (const int*)  d_in[1];
    const int*   batch = (const int*)  d_in[2];
    const float* W1 = (const float*)d_in[4];  const float* b1 = (const float*)d_in[5];
    const float* W2 = (const float*)d_in[6];  const float* b2 = (const float*)d_in[7];
    const float* W3 = (const float*)d_in[8];  const float* b3 = (const float*)d_in[9];
    const float* l1w = (const float*)d_in[10]; const float* l1b = (const float*)d_in[11];
    const float* l2w = (const float*)d_in[12]; const float* l2b = (const float*)d_in[13];
    float* out = (float*)d_out;

    static int once = 0;
    if (!once) {
        cudaFuncSetAttribute(k_gemm_tc, cudaFuncAttributeMaxDynamicSharedMemorySize, GEMM_SMEM);
        once = 1;
    }

    static __half* d_xh = nullptr;
    static __half* d_wh = nullptr;
    static __half* d_jk = nullptr;
    if (!d_xh) {
        cudaGetSymbolAddress((void**)&d_xh, g_xh);
        cudaGetSymbolAddress((void**)&d_wh, g_wh);
        cudaGetSymbolAddress((void**)&d_jk, g_jk);
    }

    k_x2h     <<<(NN*DD/4 + 255)/256, 256>>>(x);                             // 1
    k_wcvt    <<<(3*4096 + 255)/256, 256>>>(W1, W2, W3);                     // 2
    k_init    <<<(NN + 255)/256, 256>>>();                                   // 3
    k_gemm_tc <<<(NN + 127)/128, 256, GEMM_SMEM>>>(d_xh, DD, d_wh);          // 4 (profiled)
    k_deg     <<<(NE + 255)/256, 256>>>(ei);                                 // 5
    k_dinv_cnt<<<(NN + 255)/256, 256>>>(batch);                              // 6
    k_scan1   <<<NB_SCAN, 1024>>>();                                         // 7
    k_scan23  <<<(NN + 255)/256, 256>>>();                                   // 8
    k_reorder <<<(NE + 255)/256, 256>>>(ei);                                 // 9

    k_gather  <<<NN/16, 512>>>(b1, batch, 0*DD);
    k_gemm_tc <<<(NN + 127)/128, 256, GEMM_SMEM>>>(d_jk + 0*DD, JK, d_wh + 1*DD*DD);
    k_gather  <<<NN/16, 512>>>(b2, batch, 1*DD);
    k_gemm_tc <<<(NN + 127)/128, 256, GEMM_SMEM>>>(d_jk + 1*DD, JK, d_wh + 2*DD*DD);
    k_gather  <<<NN/16, 512>>>(b3, batch, 2*DD);

    k_head1<<<NG, 128>>>(l1w, l1b);
    k_head2<<<1, 64>>>(l2w, l2b, out);
}